// round 14
// baseline (speedup 1.0000x reference)
#include <cuda_runtime.h>
#include <stdint.h>
#include <math.h>

#define B_SZ 2048
#define M_SZ 512
#define N_SZ 2048
#define DIM_SZ 128
#define GATE_SZ 512
#define K_ITERS 16
#define SPLITK 2

// ---------------- scratch (static device globals; no allocation) ----------------
__device__ float g_Ahi[(size_t)M_SZ * N_SZ];
__device__ float g_Alo[(size_t)M_SZ * N_SZ];
__device__ float g_Athi[(size_t)N_SZ * M_SZ];
__device__ float g_Atlo[(size_t)N_SZ * M_SZ];
__device__ float g_bhi[(size_t)B_SZ * M_SZ];
__device__ float g_blo[(size_t)B_SZ * M_SZ];
__device__ float g_xhi[(size_t)B_SZ * N_SZ];
__device__ float g_xlo[(size_t)B_SZ * N_SZ];
__device__ float g_c[(size_t)B_SZ * N_SZ];
__device__ float g_part[SPLITK][(size_t)B_SZ * M_SZ];   // split-K partials for GEMM1
__device__ float g_gates[(size_t)B_SZ * GATE_SZ];
__device__ float g_hidden[(size_t)B_SZ * DIM_SZ];
__device__ float g_cell[(size_t)B_SZ * DIM_SZ];
__device__ float g_l1b[B_SZ];
__device__ float g_l1c[B_SZ];
__device__ float g_gamma[B_SZ];
__device__ float g_theta[B_SZ];
__device__ float g_stats[4];   // mean_b, std_b, mean_c, std_c

// ---------------- PTX helpers (all sm_80-level; compile at compute_100) --------
__device__ __forceinline__ uint32_t smem_u32(const void* p) {
    uint32_t a;
    asm("{ .reg .u64 t; cvta.to.shared.u64 t, %1; cvt.u32.u64 %0, t; }" : "=r"(a) : "l"(p));
    return a;
}
__device__ __forceinline__ float to_tf32(float x) {
    uint32_t r;
    asm("cvt.rna.tf32.f32 %0, %1;" : "=r"(r) : "f"(x));
    return __uint_as_float(r);
}
__device__ __forceinline__ void cp16(uint32_t dst, const void* src) {
    asm volatile("cp.async.cg.shared.global [%0], [%1], 16;\n" :: "r"(dst), "l"(src));
}
__device__ __forceinline__ void cp4(uint32_t dst, const float* src) {
    asm volatile("cp.async.ca.shared.global [%0], [%1], 4;\n" :: "r"(dst), "l"(src));
}
__device__ __forceinline__ void cp_commit() {
    asm volatile("cp.async.commit_group;\n" ::: "memory");
}
template<int N>
__device__ __forceinline__ void cp_wait() {
    asm volatile("cp.async.wait_group %0;\n" :: "n"(N) : "memory");
}
// m16n8k8 tf32 MMA, D += A*B (A row-major 16x8, B col-major 8x8)
__device__ __forceinline__ void mma_tf32(float* d, const uint32_t* a, const uint32_t* b) {
    asm volatile(
        "mma.sync.aligned.m16n8k8.row.col.f32.tf32.tf32.f32 "
        "{%0,%1,%2,%3}, {%4,%5,%6,%7}, {%8,%9}, {%0,%1,%2,%3};"
        : "+f"(d[0]), "+f"(d[1]), "+f"(d[2]), "+f"(d[3])
        : "r"(a[0]), "r"(a[1]), "r"(a[2]), "r"(a[3]), "r"(b[0]), "r"(b[1]));
}

// ============================================================================
// 3xTF32 NT GEMM via mma.sync: C[r,c] = sum_k X[r,k]*W[c,k], X=Xhi+Xlo etc.
// CTA: 256 threads = WM x WN warps; tile BM x BN, BK=16, cp.async double buffer.
// KLEN = K handled by this CTA; ldk = row stride of X/W; koff = blockIdx.z*KLEN.
// MODE 0: Cout = acc; fused L1 row sums (atomic)
// MODE 2: Cout(+ z offset) = acc partial; NO l1 (split-K partial pass)
// ============================================================================
template<int BM, int BN, int WM, int WN, int KLEN, int MODE>
__global__ __launch_bounds__(256, 2)
void gemm_mma(const float* __restrict__ Xhi, const float* __restrict__ Xlo,
              const float* __restrict__ Whi, const float* __restrict__ Wlo,
              int ldk,
              float* __restrict__ Cout,
              float* __restrict__ l1out, int ldo)
{
    static_assert(WM * WN == 8, "8 warps");
    constexpr int BK = 16;
    constexpr int ST = BK + 4;            // row stride in floats (20) -> conflict-free
    constexpr int SZA = BM * ST;          // floats per A part
    constexpr int SZB = BN * ST;
    constexpr int STAGEF = 2 * SZA + 2 * SZB;
    constexpr int T = KLEN / BK;
    constexpr int WTM = BM / WM;          // warp tile m (32)
    constexpr int WTN = BN / WN;          // warp tile n
    constexpr int MT  = WTM / 16;         // m-tiles per warp (2)
    constexpr int NTN = WTN / 8;          // n-tiles per warp

    extern __shared__ float sm[];

    const int tid = threadIdx.x;
    const int wid = tid >> 5;
    const int lane = tid & 31;
    const int wm = wid / WN;
    const int wn = wid % WN;
    const int ar = lane >> 2;             // 0..7
    const int ak = lane & 3;              // 0..3
    const int row0 = blockIdx.y * BM;
    const int col0 = blockIdx.x * BN;
    const int koff = blockIdx.z * KLEN;
    float* outp = (MODE == 2) ? Cout + (size_t)blockIdx.z * B_SZ * M_SZ : Cout;

    float acc[MT][NTN][4];
    #pragma unroll
    for (int mt = 0; mt < MT; mt++)
        #pragma unroll
        for (int nt = 0; nt < NTN; nt++)
            #pragma unroll
            for (int q = 0; q < 4; q++) acc[mt][nt][q] = 0.f;

    auto load_stage = [&](int t, int buf) {
        float* s = sm + buf * STAGEF;
        const int k0 = koff + t * BK;
        #pragma unroll
        for (int c = tid; c < BM * 4; c += 256) {
            int r = c >> 2, kc = c & 3;
            const size_t src = (size_t)(row0 + r) * ldk + k0 + kc * 4;
            cp16(smem_u32(s + r * ST + kc * 4), &Xhi[src]);
            cp16(smem_u32(s + SZA + r * ST + kc * 4), &Xlo[src]);
        }
        #pragma unroll
        for (int c = tid; c < BN * 4; c += 256) {
            int r = c >> 2, kc = c & 3;
            const size_t src = (size_t)(col0 + r) * ldk + k0 + kc * 4;
            cp16(smem_u32(s + 2 * SZA + r * ST + kc * 4), &Whi[src]);
            cp16(smem_u32(s + 2 * SZA + SZB + r * ST + kc * 4), &Wlo[src]);
        }
        cp_commit();
    };

    load_stage(0, 0);
    if (T > 1) load_stage(1, 1);

    for (int t = 0; t < T; t++) {
        if (t + 1 < T) cp_wait<1>(); else cp_wait<0>();
        __syncthreads();
        const float* s = sm + (t & 1) * STAGEF;
        const float* As_hi = s;
        const float* As_lo = s + SZA;
        const float* Bs_hi = s + 2 * SZA;
        const float* Bs_lo = s + 2 * SZA + SZB;

        #pragma unroll
        for (int ks = 0; ks < 2; ks++) {
            const int kk = ks * 8;
            uint32_t ahi[MT][4], alo[MT][4];
            #pragma unroll
            for (int mt = 0; mt < MT; mt++) {
                const float* pa = As_hi + (wm * WTM + mt * 16 + ar) * ST + kk + ak;
                ahi[mt][0] = __float_as_uint(pa[0]);
                ahi[mt][1] = __float_as_uint(pa[8 * ST]);
                ahi[mt][2] = __float_as_uint(pa[4]);
                ahi[mt][3] = __float_as_uint(pa[8 * ST + 4]);
                const float* pl = As_lo + (wm * WTM + mt * 16 + ar) * ST + kk + ak;
                alo[mt][0] = __float_as_uint(pl[0]);
                alo[mt][1] = __float_as_uint(pl[8 * ST]);
                alo[mt][2] = __float_as_uint(pl[4]);
                alo[mt][3] = __float_as_uint(pl[8 * ST + 4]);
            }
            #pragma unroll
            for (int nt = 0; nt < NTN; nt++) {
                uint32_t bhi[2], blo[2];
                const float* pb = Bs_hi + (wn * WTN + nt * 8 + ar) * ST + kk + ak;
                bhi[0] = __float_as_uint(pb[0]);
                bhi[1] = __float_as_uint(pb[4]);
                const float* pc = Bs_lo + (wn * WTN + nt * 8 + ar) * ST + kk + ak;
                blo[0] = __float_as_uint(pc[0]);
                blo[1] = __float_as_uint(pc[4]);
                #pragma unroll
                for (int mt = 0; mt < MT; mt++) {
                    mma_tf32(acc[mt][nt], ahi[mt], bhi);
                    mma_tf32(acc[mt][nt], ahi[mt], blo);
                    mma_tf32(acc[mt][nt], alo[mt], bhi);
                }
            }
        }
        __syncthreads();
        if (t + 2 < T) load_stage(t + 2, t & 1);
    }

    // ---------------- epilogue ----------------
    float rs[MT * 2];
    #pragma unroll
    for (int i = 0; i < MT * 2; i++) rs[i] = 0.f;
    #pragma unroll
    for (int mt = 0; mt < MT; mt++) {
        const int gr0 = row0 + wm * WTM + mt * 16 + ar;
        const int gr1 = gr0 + 8;
        #pragma unroll
        for (int nt = 0; nt < NTN; nt++) {
            const int gc = col0 + wn * WTN + nt * 8 + ak * 2;
            float v0 = acc[mt][nt][0], v1 = acc[mt][nt][1];
            float v2 = acc[mt][nt][2], v3 = acc[mt][nt][3];
            const size_t o0 = (size_t)gr0 * ldo + gc;
            const size_t o1 = (size_t)gr1 * ldo + gc;
            *(float2*)&outp[o0] = make_float2(v0, v1);
            *(float2*)&outp[o1] = make_float2(v2, v3);
            if (MODE == 0) {
                rs[mt * 2 + 0] += fabsf(v0) + fabsf(v1);
                rs[mt * 2 + 1] += fabsf(v2) + fabsf(v3);
            }
        }
    }
    if (MODE == 0) {
        #pragma unroll
        for (int i = 0; i < MT * 2; i++) {
            rs[i] += __shfl_xor_sync(0xffffffffu, rs[i], 1);
            rs[i] += __shfl_xor_sync(0xffffffffu, rs[i], 2);
        }
        if (ak == 0) {
            #pragma unroll
            for (int i = 0; i < MT * 2; i++) {
                int r = row0 + wm * WTM + (i >> 1) * 16 + (i & 1) * 8 + ar;
                atomicAdd(&l1out[r], rs[i]);
            }
        }
    }
}

// ---------------- finalize b = y - sum(partials); hi/lo split; l1b (direct) ----
__global__ void finalize_b(const float* __restrict__ y,
                           const float* __restrict__ parts,
                           float* __restrict__ bhi, float* __restrict__ blo,
                           float* __restrict__ l1b) {
    int row = blockIdx.x;
    int tid = threadIdx.x;   // 128 threads, 4 elems each
    const size_t base = (size_t)row * M_SZ + tid * 4;
    float4 yv = *(const float4*)&y[base];
    float v0 = yv.x, v1 = yv.y, v2 = yv.z, v3 = yv.w;
    #pragma unroll
    for (int z = 0; z < SPLITK; z++) {
        float4 p = *(const float4*)&parts[(size_t)z * B_SZ * M_SZ + base];
        v0 -= p.x; v1 -= p.y; v2 -= p.z; v3 -= p.w;
    }
    float h0 = to_tf32(v0), h1 = to_tf32(v1), h2 = to_tf32(v2), h3 = to_tf32(v3);
    *(float4*)&bhi[base] = make_float4(h0, h1, h2, h3);
    *(float4*)&blo[base] = make_float4(v0 - h0, v1 - h1, v2 - h2, v3 - h3);
    float s = fabsf(v0) + fabsf(v1) + fabsf(v2) + fabsf(v3);
    __shared__ float red[128];
    red[tid] = s; __syncthreads();
    for (int o = 64; o > 0; o >>= 1) {
        if (tid < o) red[tid] += red[tid + o];
        __syncthreads();
    }
    if (tid == 0) l1b[row] = red[0];
}

// ---------------- prologue: split A into hi/lo + transposed hi/lo ----------------
__global__ void split_A(const float* __restrict__ A,
                        float* __restrict__ Ahi, float* __restrict__ Alo,
                        float* __restrict__ Athi, float* __restrict__ Atlo) {
    __shared__ float th[32][33], tl[32][33];
    int n0 = blockIdx.x * 32, m0 = blockIdx.y * 32;
    int tx = threadIdx.x, ty = threadIdx.y;   // block (32, 8)
    #pragma unroll
    for (int i = 0; i < 32; i += 8) {
        size_t idx = (size_t)(m0 + ty + i) * N_SZ + n0 + tx;
        float a = A[idx];
        float h = to_tf32(a), l = a - h;
        Ahi[idx] = h; Alo[idx] = l;
        th[ty + i][tx] = h; tl[ty + i][tx] = l;
    }
    __syncthreads();
    #pragma unroll
    for (int i = 0; i < 32; i += 8) {
        size_t idx = (size_t)(n0 + ty + i) * M_SZ + m0 + tx;
        Athi[idx] = th[tx][ty + i];
        Atlo[idx] = tl[tx][ty + i];
    }
}

// ---------------- iter 0: b = y; write hi/lo split + l1b ----------------
__global__ void split_y(const float* __restrict__ y,
                        float* __restrict__ bhi, float* __restrict__ blo,
                        float* __restrict__ l1b) {
    int row = blockIdx.x;
    int tid = threadIdx.x;   // 128
    const float* p = y + (size_t)row * M_SZ;
    float4 v = *(const float4*)&p[tid * 4];
    float h0 = to_tf32(v.x), h1 = to_tf32(v.y), h2 = to_tf32(v.z), h3 = to_tf32(v.w);
    *(float4*)&bhi[(size_t)row * M_SZ + tid * 4] = make_float4(h0, h1, h2, h3);
    *(float4*)&blo[(size_t)row * M_SZ + tid * 4] = make_float4(v.x - h0, v.y - h1, v.z - h2, v.w - h3);
    float s = fabsf(v.x) + fabsf(v.y) + fabsf(v.z) + fabsf(v.w);
    __shared__ float red[128];
    red[tid] = s; __syncthreads();
    for (int o = 64; o > 0; o >>= 1) {
        if (tid < o) red[tid] += red[tid + o];
        __syncthreads();
    }
    if (tid == 0) l1b[row] = red[0];
}

// ---------------- init hidden/cell from h0/c0 ----------------
__global__ void init_hc(const float* __restrict__ h0, const float* __restrict__ c0,
                        float* __restrict__ hidden, float* __restrict__ cell) {
    int idx = blockIdx.x * blockDim.x + threadIdx.x;
    if (idx < B_SZ * DIM_SZ) {
        int j = idx & (DIM_SZ - 1);
        hidden[idx] = h0[j];
        cell[idx] = c0[j];
    }
}

// ---------------- SIMT NT GEMM (LSTM gates only) ----------------
// MODE 2: C = acc + s0*Wih[c,0]+s1*Wih[c,1]+bih[c]+bhh[c]
template<int BM, int BN, int BK, int TM, int TN, int MODE, int FUSE_L1>
__global__ __launch_bounds__((BM/TM)*(BN/TN), 2)
void gemm_cp(const float* __restrict__ X, int ldx,
             const float* __restrict__ W, int ldw,
             int K,
             const float* __restrict__ Yin,
             const float* __restrict__ Wih,
             const float* __restrict__ bih,
             const float* __restrict__ bhh,
             float* __restrict__ C, int ldc,
             float* __restrict__ l1out)
{
    constexpr int TPB = (BM/TM)*(BN/TN);
    constexpr int BMP = BM + 4;
    constexpr int BNP = BN + 4;
    constexpr int XE = BM*BK/TPB;
    constexpr int WE = BN*BK/TPB;

    __shared__ float Xs[2][BK][BMP];
    __shared__ float Ws[2][BK][BNP];

    const int tid = threadIdx.x;
    const int tx = tid % (BN/TN);
    const int ty = tid / (BN/TN);
    const int row0 = blockIdx.y * BM;
    const int col0 = blockIdx.x * BN;

    uint32_t xb[2], wb[2];
    xb[0] = smem_u32(&Xs[0][0][0]); xb[1] = smem_u32(&Xs[1][0][0]);
    wb[0] = smem_u32(&Ws[0][0][0]); wb[1] = smem_u32(&Ws[1][0][0]);

    float acc[TM][TN];
    #pragma unroll
    for (int i = 0; i < TM; i++)
        #pragma unroll
        for (int j = 0; j < TN; j++) acc[i][j] = 0.f;

    const int T = K / BK;

    auto issue_stage = [&](int stage, int buf) {
        const int k0 = stage * BK;
        #pragma unroll
        for (int v = 0; v < XE; v++) {
            int t2 = tid + v*TPB;
            int kq = t2 % BK, r = t2 / BK;
            cp4(xb[buf] + (uint32_t)((kq*BMP + r) * 4),
                &X[(size_t)(row0 + r) * ldx + k0 + kq]);
        }
        #pragma unroll
        for (int v = 0; v < WE; v++) {
            int t2 = tid + v*TPB;
            int kq = t2 % BK, r = t2 / BK;
            cp4(wb[buf] + (uint32_t)((kq*BNP + r) * 4),
                &W[(size_t)(col0 + r) * ldw + k0 + kq]);
        }
        cp_commit();
    };

    issue_stage(0, 0);
    if (T > 1) issue_stage(1, 1);

    for (int t = 0; t < T; t++) {
        if (t + 1 < T) cp_wait<1>(); else cp_wait<0>();
        __syncthreads();
        const int buf = t & 1;
        #pragma unroll
        for (int kk = 0; kk < BK; kk++) {
            float xm[TM], wn[TN];
            #pragma unroll
            for (int i = 0; i < TM; i += 4)
                *(float4*)&xm[i] = *(const float4*)&Xs[buf][kk][ty*TM + i];
            #pragma unroll
            for (int j = 0; j < TN; j += 4)
                *(float4*)&wn[j] = *(const float4*)&Ws[buf][kk][tx*TN + j];
            #pragma unroll
            for (int i = 0; i < TM; i++)
                #pragma unroll
                for (int j = 0; j < TN; j++)
                    acc[i][j] = fmaf(xm[i], wn[j], acc[i][j]);
        }
        __syncthreads();
        if (t + 2 < T) issue_stage(t + 2, buf);
    }

    #pragma unroll
    for (int i = 0; i < TM; i++) {
        int row = row0 + ty*TM + i;
        float s0 = 0.f, s1 = 0.f;
        if (MODE == 2) {
            s0 = (g_l1b[row] - g_stats[0]) / g_stats[1];
            s1 = (g_l1c[row] - g_stats[2]) / g_stats[3];
        }
        #pragma unroll
        for (int jj = 0; jj < TN; jj += 4) {
            int col = col0 + tx*TN + jj;
            float4 o;
            float* ov = (float*)&o;
            #pragma unroll
            for (int q = 0; q < 4; q++) {
                float v = acc[i][jj + q];
                if (MODE == 2) {
                    int cq = col + q;
                    v += s0 * Wih[cq*2 + 0] + s1 * Wih[cq*2 + 1]
                       + bih[cq] + bhh[cq];
                }
                ov[q] = v;
            }
            *(float4*)&C[(size_t)row * ldc + col] = o;
        }
    }
}

// ---------------- stats (mean + ddof=1 std), double accumulation ----------------
__global__ void stats_kernel(const float* __restrict__ l1b,
                             const float* __restrict__ l1c,
                             float* __restrict__ stats) {
    int tid = threadIdx.x;
    double sb = 0, sb2 = 0, sc = 0, sc2 = 0;
    for (int i = tid; i < B_SZ; i += 256) {
        double v = (double)l1b[i]; sb += v; sb2 += v*v;
        double w = (double)l1c[i]; sc += w; sc2 += w*w;
    }
    __shared__ double red[256];
    auto reduce = [&](double v) -> double {
        red[tid] = v; __syncthreads();
        for (int o = 128; o > 0; o >>= 1) {
            if (tid < o) red[tid] += red[tid + o];
            __syncthreads();
        }
        double r = red[0]; __syncthreads();
        return r;
    };
    double Sb = reduce(sb), Sb2 = reduce(sb2), Sc = reduce(sc), Sc2 = reduce(sc2);
    if (tid == 0) {
        double nb = (double)B_SZ;
        double mb = Sb / nb, mc = Sc / nb;
        double vb = (Sb2 - Sb*Sb/nb) / (nb - 1.0);
        double vc = (Sc2 - Sc*Sc/nb) / (nb - 1.0);
        stats[0] = (float)mb; stats[1] = (float)sqrt(vb);
        stats[2] = (float)mc; stats[3] = (float)sqrt(vc);
    }
}

// ---------------- LSTM pointwise + output head: warp-per-row, no block syncs ----
__global__ __launch_bounds__(256, 4)
void lstm_update(const float* __restrict__ gates,
                 const float* __restrict__ Wlll, const float* __restrict__ blll,
                 const float* __restrict__ Wlin, const float* __restrict__ blin,
                 float* __restrict__ hidden, float* __restrict__ cell,
                 float* __restrict__ gamma, float* __restrict__ theta)
{
    const int warp = threadIdx.x >> 5;
    const int lane = threadIdx.x & 31;
    const int bi = blockIdx.x * 8 + warp;   // one row per warp
    __shared__ float c2s[8][DIM_SZ];

    const float* g = gates + (size_t)bi * GATE_SZ;

    #pragma unroll
    for (int q = 0; q < 4; q++) {
        int j = lane + 32 * q;
        float gi = g[j], gf = g[DIM_SZ + j], gg = g[2*DIM_SZ + j], go = g[3*DIM_SZ + j];
        float cprev = cell[(size_t)bi * DIM_SZ + j];
        float ii = 1.f / (1.f + expf(-gi));
        float ff = 1.f / (1.f + expf(-gf));
        float oo = 1.f / (1.f + expf(-go));
        float c2 = ff * cprev + ii * tanhf(gg);
        float h2 = oo * tanhf(c2);
        cell[(size_t)bi * DIM_SZ + j] = c2;
        hidden[(size_t)bi * DIM_SZ + j] = h2;
        c2s[warp][j] = c2;
    }
    __syncwarp();

    float acc0 = 0.f, acc1 = 0.f;
    #pragma unroll
    for (int q = 0; q < 4; q++) {
        int j = lane + 32 * q;
        float a = blll[j];
        #pragma unroll 8
        for (int k = 0; k < DIM_SZ; k++)
            a = fmaf(c2s[warp][k], __ldg(&Wlll[j * DIM_SZ + k]), a);
        float m = fmaxf(a, 0.f);
        acc0 = fmaf(m, __ldg(&Wlin[j]), acc0);
        acc1 = fmaf(m, __ldg(&Wlin[DIM_SZ + j]), acc1);
    }
    #pragma unroll
    for (int o = 16; o > 0; o >>= 1) {
        acc0 += __shfl_xor_sync(0xffffffffu, acc0, o);
        acc1 += __shfl_xor_sync(0xffffffffu, acc1, o);
    }
    if (lane == 0) {
        float a0 = acc0 + blin[0], a1 = acc1 + blin[1];
        gamma[bi] = fmaxf(a0, 0.f) + log1pf(expf(-fabsf(a0)));
        theta[bi] = fmaxf(a1, 0.f) + log1pf(expf(-fabsf(a1)));
    }
}

// ---------------- soft-threshold with top-p keep + tf32 split of x ----------------
// Reads x as xhi+xlo (exact). Writes x only when WRITE_X (last iter).
// Zeroes l1c[bi] for the next iteration's GEMM2 atomics. Plain shared-atomic
// histogram (match_any aggregation measured slower in R13).
template<int WRITE_X>
__global__ void threshold_kernel(const float* __restrict__ c, float* __restrict__ x,
                                 float* __restrict__ xhi, float* __restrict__ xlo,
                                 const float* __restrict__ gamma,
                                 const float* __restrict__ theta,
                                 float* __restrict__ l1c, int p)
{
    int bi = blockIdx.x;
    int tid = threadIdx.x;   // 256 threads, 8 elems each
    float gm = gamma[bi], th = theta[bi];
    const float* crow = c + (size_t)bi * N_SZ;
    float* xrow = x + (size_t)bi * N_SZ;
    float* hrow = xhi + (size_t)bi * N_SZ;
    float* lrow = xlo + (size_t)bi * N_SZ;

    float dv[8]; unsigned ab[8];
    #pragma unroll
    for (int e = 0; e < 8; e++) {
        int idx = tid + e * 256;
        float xv = hrow[idx] + lrow[idx];   // == x exactly (hi+lo reconstruction)
        float d = fmaf(gm, crow[idx], xv);
        dv[e] = d;
        ab[e] = __float_as_uint(fabsf(d));
    }
    if (tid == 0) l1c[bi] = 0.f;   // reset for next iteration's atomics

    __shared__ int hist[256];
    __shared__ unsigned sh_pref;
    __shared__ int sh_k;
    unsigned prefix = 0; int k = p;

    for (int pass = 0; pass < 4; pass++) {
        int shift = 24 - 8 * pass;
        hist[tid] = 0;
        __syncthreads();
        #pragma unroll
        for (int e = 0; e < 8; e++) {
            if ((unsigned)(((unsigned long long)ab[e]) >> (shift + 8)) == prefix)
                atomicAdd(&hist[(ab[e] >> shift) & 255], 1);
        }
        __syncthreads();
        if (tid == 0) {
            int cum = 0, bsel = 0;
            for (int b = 255; b >= 0; b--) {
                cum += hist[b];
                if (cum >= k) { bsel = b; break; }
            }
            k -= (cum - hist[bsel]);
            prefix = (prefix << 8) | (unsigned)bsel;
            sh_pref = prefix; sh_k = k;
        }
        __syncthreads();
        prefix = sh_pref; k = sh_k;
        __syncthreads();
    }

    float thresh = __uint_as_float(prefix);
    #pragma unroll
    for (int e = 0; e < 8; e++) {
        int idx = tid + e * 256;
        float d = dv[e], ad = fabsf(d);
        float soft = copysignf(fmaxf(ad - th, 0.f), d);
        float val = (ad > thresh) ? d : soft;
        if (WRITE_X) xrow[idx] = val;
        float h = to_tf32(val);
        hrow[idx] = h;
        lrow[idx] = val - h;
    }
}

// ---------------- host driver (graph-capturable) ----------------
extern "C" void kernel_launch(void* const* d_in, const int* in_sizes, int n_in,
                              void* d_out, int out_size)
{
    const float* y     = (const float*)d_in[0];
    const float* A     = (const float*)d_in[1];
    const float* W_ih  = (const float*)d_in[2];
    const float* W_hh  = (const float*)d_in[3];
    const float* b_ih  = (const float*)d_in[4];
    const float* b_hh  = (const float*)d_in[5];
    const float* W_lll = (const float*)d_in[6];
    const float* b_lll = (const float*)d_in[7];
    const float* W_lin = (const float*)d_in[8];
    const float* b_lin = (const float*)d_in[9];
    const float* h0    = (const float*)d_in[10];
    const float* c0    = (const float*)d_in[11];
    float* x = (float*)d_out;

    float *Ahi, *Alo, *Athi, *Atlo, *bhi, *blo, *xhi, *xlo, *cc, *part;
    float *gates, *hid, *cel, *l1b, *l1c, *gam, *the, *stats;
    cudaGetSymbolAddress((void**)&Ahi,  g_Ahi);
    cudaGetSymbolAddress((void**)&Alo,  g_Alo);
    cudaGetSymbolAddress((void**)&Athi, g_Athi);
    cudaGetSymbolAddress((void**)&Atlo, g_Atlo);
    cudaGetSymbolAddress((void**)&bhi,  g_bhi);
    cudaGetSymbolAddress((void**)&blo,  g_blo);
    cudaGetSymbolAddress((void**)&xhi,  g_xhi);
    cudaGetSymbolAddress((void**)&xlo,  g_xlo);
    cudaGetSymbolAddress((void**)&cc,   g_c);
    cudaGetSymbolAddress((void**)&part, g_part);
    cudaGetSymbolAddress((void**)&gates, g_gates);
    cudaGetSymbolAddress((void**)&hid,  g_hidden);
    cudaGetSymbolAddress((void**)&cel,  g_cell);
    cudaGetSymbolAddress((void**)&l1b,  g_l1b);
    cudaGetSymbolAddress((void**)&l1c,  g_l1c);
    cudaGetSymbolAddress((void**)&gam,  g_gamma);
    cudaGetSymbolAddress((void**)&the,  g_theta);
    cudaGetSymbolAddress((void**)&stats, g_stats);

    // dynamic smem (bytes): stage = (2*BM*20 + 2*BN*20) floats, double-buffered
    constexpr int SMEM1 = 2 * (2 * 128 * 20 + 2 * 64  * 20) * 4;   // 61440 B (128x64)
    constexpr int SMEM2 = 2 * (2 * 128 * 20 + 2 * 128 * 20) * 4;   // 81920 B (128x128)
    cudaFuncSetAttribute((const void*)gemm_mma<128, 64, 4, 2, N_SZ / SPLITK, 2>,
                         cudaFuncAttributeMaxDynamicSharedMemorySize, SMEM1);
    cudaFuncSetAttribute((const void*)gemm_mma<128, 128, 4, 2, M_SZ, 0>,
                         cudaFuncAttributeMaxDynamicSharedMemorySize, SMEM2);

    cudaMemsetAsync(x, 0, sizeof(float) * (size_t)B_SZ * N_SZ, 0);
    cudaMemsetAsync(xhi, 0, sizeof(float) * (size_t)B_SZ * N_SZ, 0);
    cudaMemsetAsync(xlo, 0, sizeof(float) * (size_t)B_SZ * N_SZ, 0);
    cudaMemsetAsync(l1c, 0, B_SZ * sizeof(float), 0);
    split_A<<<dim3(N_SZ/32, M_SZ/32), dim3(32, 8)>>>(A, Ahi, Alo, Athi, Atlo);
    init_hc<<<(B_SZ*DIM_SZ + 255)/256, 256>>>(h0, c0, hid, cel);

    // s_sched = clip(linspace(S/K, S*1.4, K), 0, S*1.2).astype(int32)
    static const int sched[K_ITERS] = {6, 15, 24, 33, 41, 50, 59, 68,
                                       77, 86, 95, 104, 113, 120, 120, 120};

    for (int it = 0; it < K_ITERS; ++it) {
        if (it == 0) {
            split_y<<<B_SZ, 128>>>(y, bhi, blo, l1b);   // b = y, l1b direct
        } else {
            // partials = x@A^T over K halves: 128x64 tiles, grid (8,16,2) = 256 CTAs
            gemm_mma<128, 64, 4, 2, N_SZ / SPLITK, 2>
                <<<dim3(M_SZ/64, B_SZ/128, SPLITK), 256, SMEM1>>>(
                xhi, xlo, Ahi, Alo, N_SZ, part, nullptr, M_SZ);
            // b = y - sum partials; hi/lo split; l1b (direct write, no memset)
            finalize_b<<<B_SZ, 128>>>(y, part, bhi, blo, l1b);
        }

        // c = b @ A  (rows=B, cols=N, K=M); 128x128 tiles -> 256 CTAs
        // (l1c was zeroed by previous threshold_kernel / initial memset)
        gemm_mma<128, 128, 4, 2, M_SZ, 0><<<dim3(N_SZ/128, B_SZ/128), 256, SMEM2>>>(
            bhi, blo, Athi, Atlo, M_SZ, cc, l1c, N_SZ);

        if (it == 0) stats_kernel<<<1, 256>>>(l1b, l1c, stats);

        // gates = stack @ W_ih^T + b_ih + hidden @ W_hh^T + b_hh
        gemm_cp<64,64,16,4,4,2,0><<<dim3(GATE_SZ/64, B_SZ/64), 256>>>(
            hid, DIM_SZ, W_hh, DIM_SZ, DIM_SZ, nullptr, W_ih, b_ih, b_hh, gates, GATE_SZ, nullptr);

        lstm_update<<<B_SZ/8, 256>>>(gates, W_lll, b_lll, W_lin, b_lin,
                                     hid, cel, gam, the);

        // d = (xhi+xlo) + gamma*c; top-p soft threshold; write xhi/xlo (+x last)
        if (it == K_ITERS - 1)
            threshold_kernel<1><<<B_SZ, 256>>>(cc, x, xhi, xlo, gam, the, l1c, sched[it]);
        else
            threshold_kernel<0><<<B_SZ, 256>>>(cc, x, xhi, xlo, gam, the, l1c, sched[it]);
    }
}

// round 15
// speedup vs baseline: 1.0381x; 1.0381x over previous
#include <cuda_runtime.h>
#include <stdint.h>
#include <math.h>

#define B_SZ 2048
#define M_SZ 512
#define N_SZ 2048
#define DIM_SZ 128
#define GATE_SZ 512
#define K_ITERS 16
#define SPLITK 2

// ---------------- scratch (static device globals; no allocation) ----------------
__device__ float g_Ahi[(size_t)M_SZ * N_SZ];
__device__ float g_Alo[(size_t)M_SZ * N_SZ];
__device__ float g_Athi[(size_t)N_SZ * M_SZ];
__device__ float g_Atlo[(size_t)N_SZ * M_SZ];
__device__ float g_bhi[(size_t)B_SZ * M_SZ];
__device__ float g_blo[(size_t)B_SZ * M_SZ];
__device__ float g_xhi[(size_t)B_SZ * N_SZ];
__device__ float g_xlo[(size_t)B_SZ * N_SZ];
__device__ float g_c[(size_t)B_SZ * N_SZ];
__device__ float g_part[SPLITK][(size_t)B_SZ * M_SZ];   // split-K partials for GEMM1
__device__ float g_gates[(size_t)B_SZ * GATE_SZ];
__device__ float g_hidden[(size_t)B_SZ * DIM_SZ];
__device__ float g_cell[(size_t)B_SZ * DIM_SZ];
__device__ float g_l1b[B_SZ];
__device__ float g_l1c[B_SZ];
__device__ float g_gamma[B_SZ];
__device__ float g_theta[B_SZ];
__device__ float g_stats[4];   // mean_b, std_b, mean_c, std_c

// ---------------- PTX helpers (all sm_80-level; compile at compute_100) --------
__device__ __forceinline__ uint32_t smem_u32(const void* p) {
    uint32_t a;
    asm("{ .reg .u64 t; cvta.to.shared.u64 t, %1; cvt.u32.u64 %0, t; }" : "=r"(a) : "l"(p));
    return a;
}
__device__ __forceinline__ float to_tf32(float x) {
    uint32_t r;
    asm("cvt.rna.tf32.f32 %0, %1;" : "=r"(r) : "f"(x));
    return __uint_as_float(r);
}
__device__ __forceinline__ void cp16(uint32_t dst, const void* src) {
    asm volatile("cp.async.cg.shared.global [%0], [%1], 16;\n" :: "r"(dst), "l"(src));
}
__device__ __forceinline__ void cp4(uint32_t dst, const float* src) {
    asm volatile("cp.async.ca.shared.global [%0], [%1], 4;\n" :: "r"(dst), "l"(src));
}
__device__ __forceinline__ void cp_commit() {
    asm volatile("cp.async.commit_group;\n" ::: "memory");
}
template<int N>
__device__ __forceinline__ void cp_wait() {
    asm volatile("cp.async.wait_group %0;\n" :: "n"(N) : "memory");
}
// m16n8k8 tf32 MMA, D += A*B (A row-major 16x8, B col-major 8x8)
__device__ __forceinline__ void mma_tf32(float* d, const uint32_t* a, const uint32_t* b) {
    asm volatile(
        "mma.sync.aligned.m16n8k8.row.col.f32.tf32.tf32.f32 "
        "{%0,%1,%2,%3}, {%4,%5,%6,%7}, {%8,%9}, {%0,%1,%2,%3};"
        : "+f"(d[0]), "+f"(d[1]), "+f"(d[2]), "+f"(d[3])
        : "r"(a[0]), "r"(a[1]), "r"(a[2]), "r"(a[3]), "r"(b[0]), "r"(b[1]));
}

// ============================================================================
// 3xTF32 NT GEMM via mma.sync: C[r,c] = sum_k X[r,k]*W[c,k], X=Xhi+Xlo etc.
// CTA: 256 threads = WM x WN warps; tile BM x BN, BK=16, cp.async double buffer.
// KLEN = K handled by this CTA; ldk = row stride of X/W; koff = blockIdx.z*KLEN.
// MODE 0: Cout = acc; fused L1 row sums (atomic)
// MODE 2: Cout(+ z offset) = acc partial; NO l1 (split-K partial pass)
// ============================================================================
template<int BM, int BN, int WM, int WN, int KLEN, int MODE>
__global__ __launch_bounds__(256, 2)
void gemm_mma(const float* __restrict__ Xhi, const float* __restrict__ Xlo,
              const float* __restrict__ Whi, const float* __restrict__ Wlo,
              int ldk,
              float* __restrict__ Cout,
              float* __restrict__ l1out, int ldo)
{
    static_assert(WM * WN == 8, "8 warps");
    constexpr int BK = 16;
    constexpr int ST = BK + 4;            // row stride in floats (20) -> conflict-free
    constexpr int SZA = BM * ST;          // floats per A part
    constexpr int SZB = BN * ST;
    constexpr int STAGEF = 2 * SZA + 2 * SZB;
    constexpr int T = KLEN / BK;
    constexpr int WTM = BM / WM;          // warp tile m (32)
    constexpr int WTN = BN / WN;          // warp tile n
    constexpr int MT  = WTM / 16;         // m-tiles per warp (2)
    constexpr int NTN = WTN / 8;          // n-tiles per warp

    extern __shared__ float sm[];

    const int tid = threadIdx.x;
    const int wid = tid >> 5;
    const int lane = tid & 31;
    const int wm = wid / WN;
    const int wn = wid % WN;
    const int ar = lane >> 2;             // 0..7
    const int ak = lane & 3;              // 0..3
    const int row0 = blockIdx.y * BM;
    const int col0 = blockIdx.x * BN;
    const int koff = blockIdx.z * KLEN;
    float* outp = (MODE == 2) ? Cout + (size_t)blockIdx.z * B_SZ * M_SZ : Cout;

    float acc[MT][NTN][4];
    #pragma unroll
    for (int mt = 0; mt < MT; mt++)
        #pragma unroll
        for (int nt = 0; nt < NTN; nt++)
            #pragma unroll
            for (int q = 0; q < 4; q++) acc[mt][nt][q] = 0.f;

    auto load_stage = [&](int t, int buf) {
        float* s = sm + buf * STAGEF;
        const int k0 = koff + t * BK;
        #pragma unroll
        for (int c = tid; c < BM * 4; c += 256) {
            int r = c >> 2, kc = c & 3;
            const size_t src = (size_t)(row0 + r) * ldk + k0 + kc * 4;
            cp16(smem_u32(s + r * ST + kc * 4), &Xhi[src]);
            cp16(smem_u32(s + SZA + r * ST + kc * 4), &Xlo[src]);
        }
        #pragma unroll
        for (int c = tid; c < BN * 4; c += 256) {
            int r = c >> 2, kc = c & 3;
            const size_t src = (size_t)(col0 + r) * ldk + k0 + kc * 4;
            cp16(smem_u32(s + 2 * SZA + r * ST + kc * 4), &Whi[src]);
            cp16(smem_u32(s + 2 * SZA + SZB + r * ST + kc * 4), &Wlo[src]);
        }
        cp_commit();
    };

    load_stage(0, 0);
    if (T > 1) load_stage(1, 1);

    for (int t = 0; t < T; t++) {
        if (t + 1 < T) cp_wait<1>(); else cp_wait<0>();
        __syncthreads();
        const float* s = sm + (t & 1) * STAGEF;
        const float* As_hi = s;
        const float* As_lo = s + SZA;
        const float* Bs_hi = s + 2 * SZA;
        const float* Bs_lo = s + 2 * SZA + SZB;

        #pragma unroll
        for (int ks = 0; ks < 2; ks++) {
            const int kk = ks * 8;
            uint32_t ahi[MT][4], alo[MT][4];
            #pragma unroll
            for (int mt = 0; mt < MT; mt++) {
                const float* pa = As_hi + (wm * WTM + mt * 16 + ar) * ST + kk + ak;
                ahi[mt][0] = __float_as_uint(pa[0]);
                ahi[mt][1] = __float_as_uint(pa[8 * ST]);
                ahi[mt][2] = __float_as_uint(pa[4]);
                ahi[mt][3] = __float_as_uint(pa[8 * ST + 4]);
                const float* pl = As_lo + (wm * WTM + mt * 16 + ar) * ST + kk + ak;
                alo[mt][0] = __float_as_uint(pl[0]);
                alo[mt][1] = __float_as_uint(pl[8 * ST]);
                alo[mt][2] = __float_as_uint(pl[4]);
                alo[mt][3] = __float_as_uint(pl[8 * ST + 4]);
            }
            #pragma unroll
            for (int nt = 0; nt < NTN; nt++) {
                uint32_t bhi[2], blo[2];
                const float* pb = Bs_hi + (wn * WTN + nt * 8 + ar) * ST + kk + ak;
                bhi[0] = __float_as_uint(pb[0]);
                bhi[1] = __float_as_uint(pb[4]);
                const float* pc = Bs_lo + (wn * WTN + nt * 8 + ar) * ST + kk + ak;
                blo[0] = __float_as_uint(pc[0]);
                blo[1] = __float_as_uint(pc[4]);
                #pragma unroll
                for (int mt = 0; mt < MT; mt++) {
                    mma_tf32(acc[mt][nt], ahi[mt], bhi);
                    mma_tf32(acc[mt][nt], ahi[mt], blo);
                    mma_tf32(acc[mt][nt], alo[mt], bhi);
                }
            }
        }
        __syncthreads();
        if (t + 2 < T) load_stage(t + 2, t & 1);
    }

    // ---------------- epilogue ----------------
    float rs[MT * 2];
    #pragma unroll
    for (int i = 0; i < MT * 2; i++) rs[i] = 0.f;
    #pragma unroll
    for (int mt = 0; mt < MT; mt++) {
        const int gr0 = row0 + wm * WTM + mt * 16 + ar;
        const int gr1 = gr0 + 8;
        #pragma unroll
        for (int nt = 0; nt < NTN; nt++) {
            const int gc = col0 + wn * WTN + nt * 8 + ak * 2;
            float v0 = acc[mt][nt][0], v1 = acc[mt][nt][1];
            float v2 = acc[mt][nt][2], v3 = acc[mt][nt][3];
            const size_t o0 = (size_t)gr0 * ldo + gc;
            const size_t o1 = (size_t)gr1 * ldo + gc;
            *(float2*)&outp[o0] = make_float2(v0, v1);
            *(float2*)&outp[o1] = make_float2(v2, v3);
            if (MODE == 0) {
                rs[mt * 2 + 0] += fabsf(v0) + fabsf(v1);
                rs[mt * 2 + 1] += fabsf(v2) + fabsf(v3);
            }
        }
    }
    if (MODE == 0) {
        #pragma unroll
        for (int i = 0; i < MT * 2; i++) {
            rs[i] += __shfl_xor_sync(0xffffffffu, rs[i], 1);
            rs[i] += __shfl_xor_sync(0xffffffffu, rs[i], 2);
        }
        if (ak == 0) {
            #pragma unroll
            for (int i = 0; i < MT * 2; i++) {
                int r = row0 + wm * WTM + (i >> 1) * 16 + (i & 1) * 8 + ar;
                atomicAdd(&l1out[r], rs[i]);
            }
        }
    }
}

// ---------------- finalize b = y - sum(partials); hi/lo split; l1b (direct) ----
// Also zeroes l1c[row] ahead of GEMM2's atomics (same-stream ordering).
__global__ void finalize_b(const float* __restrict__ y,
                           const float* __restrict__ parts,
                           float* __restrict__ bhi, float* __restrict__ blo,
                           float* __restrict__ l1b, float* __restrict__ l1c) {
    int row = blockIdx.x;
    int tid = threadIdx.x;   // 128 threads, 4 elems each
    const size_t base = (size_t)row * M_SZ + tid * 4;
    float4 yv = *(const float4*)&y[base];
    float v0 = yv.x, v1 = yv.y, v2 = yv.z, v3 = yv.w;
    #pragma unroll
    for (int z = 0; z < SPLITK; z++) {
        float4 p = *(const float4*)&parts[(size_t)z * B_SZ * M_SZ + base];
        v0 -= p.x; v1 -= p.y; v2 -= p.z; v3 -= p.w;
    }
    float h0 = to_tf32(v0), h1 = to_tf32(v1), h2 = to_tf32(v2), h3 = to_tf32(v3);
    *(float4*)&bhi[base] = make_float4(h0, h1, h2, h3);
    *(float4*)&blo[base] = make_float4(v0 - h0, v1 - h1, v2 - h2, v3 - h3);
    float s = fabsf(v0) + fabsf(v1) + fabsf(v2) + fabsf(v3);
    __shared__ float red[128];
    red[tid] = s; __syncthreads();
    for (int o = 64; o > 0; o >>= 1) {
        if (tid < o) red[tid] += red[tid + o];
        __syncthreads();
    }
    if (tid == 0) { l1b[row] = red[0]; l1c[row] = 0.f; }
}

// ---------------- prologue: split A into hi/lo + transposed hi/lo ----------------
__global__ void split_A(const float* __restrict__ A,
                        float* __restrict__ Ahi, float* __restrict__ Alo,
                        float* __restrict__ Athi, float* __restrict__ Atlo) {
    __shared__ float th[32][33], tl[32][33];
    int n0 = blockIdx.x * 32, m0 = blockIdx.y * 32;
    int tx = threadIdx.x, ty = threadIdx.y;   // block (32, 8)
    #pragma unroll
    for (int i = 0; i < 32; i += 8) {
        size_t idx = (size_t)(m0 + ty + i) * N_SZ + n0 + tx;
        float a = A[idx];
        float h = to_tf32(a), l = a - h;
        Ahi[idx] = h; Alo[idx] = l;
        th[ty + i][tx] = h; tl[ty + i][tx] = l;
    }
    __syncthreads();
    #pragma unroll
    for (int i = 0; i < 32; i += 8) {
        size_t idx = (size_t)(n0 + ty + i) * M_SZ + m0 + tx;
        Athi[idx] = th[tx][ty + i];
        Atlo[idx] = tl[tx][ty + i];
    }
}

// ---------------- iter 0: b = y; hi/lo split + l1b; zero l1c ----------------
__global__ void split_y(const float* __restrict__ y,
                        float* __restrict__ bhi, float* __restrict__ blo,
                        float* __restrict__ l1b, float* __restrict__ l1c) {
    int row = blockIdx.x;
    int tid = threadIdx.x;   // 128
    const float* p = y + (size_t)row * M_SZ;
    float4 v = *(const float4*)&p[tid * 4];
    float h0 = to_tf32(v.x), h1 = to_tf32(v.y), h2 = to_tf32(v.z), h3 = to_tf32(v.w);
    *(float4*)&bhi[(size_t)row * M_SZ + tid * 4] = make_float4(h0, h1, h2, h3);
    *(float4*)&blo[(size_t)row * M_SZ + tid * 4] = make_float4(v.x - h0, v.y - h1, v.z - h2, v.w - h3);
    float s = fabsf(v.x) + fabsf(v.y) + fabsf(v.z) + fabsf(v.w);
    __shared__ float red[128];
    red[tid] = s; __syncthreads();
    for (int o = 64; o > 0; o >>= 1) {
        if (tid < o) red[tid] += red[tid + o];
        __syncthreads();
    }
    if (tid == 0) { l1b[row] = red[0]; l1c[row] = 0.f; }
}

// ---------------- init hidden/cell from h0/c0 ----------------
__global__ void init_hc(const float* __restrict__ h0, const float* __restrict__ c0,
                        float* __restrict__ hidden, float* __restrict__ cell) {
    int idx = blockIdx.x * blockDim.x + threadIdx.x;
    if (idx < B_SZ * DIM_SZ) {
        int j = idx & (DIM_SZ - 1);
        hidden[idx] = h0[j];
        cell[idx] = c0[j];
    }
}

// ---------------- SIMT NT GEMM (LSTM gates only) ----------------
// MODE 2: C = acc + s0*Wih[c,0]+s1*Wih[c,1]+bih[c]+bhh[c]
template<int BM, int BN, int BK, int TM, int TN, int MODE, int FUSE_L1>
__global__ __launch_bounds__((BM/TM)*(BN/TN), 2)
void gemm_cp(const float* __restrict__ X, int ldx,
             const float* __restrict__ W, int ldw,
             int K,
             const float* __restrict__ Yin,
             const float* __restrict__ Wih,
             const float* __restrict__ bih,
             const float* __restrict__ bhh,
             float* __restrict__ C, int ldc,
             float* __restrict__ l1out)
{
    constexpr int TPB = (BM/TM)*(BN/TN);
    constexpr int BMP = BM + 4;
    constexpr int BNP = BN + 4;
    constexpr int XE = BM*BK/TPB;
    constexpr int WE = BN*BK/TPB;

    __shared__ float Xs[2][BK][BMP];
    __shared__ float Ws[2][BK][BNP];

    const int tid = threadIdx.x;
    const int tx = tid % (BN/TN);
    const int ty = tid / (BN/TN);
    const int row0 = blockIdx.y * BM;
    const int col0 = blockIdx.x * BN;

    uint32_t xb[2], wb[2];
    xb[0] = smem_u32(&Xs[0][0][0]); xb[1] = smem_u32(&Xs[1][0][0]);
    wb[0] = smem_u32(&Ws[0][0][0]); wb[1] = smem_u32(&Ws[1][0][0]);

    float acc[TM][TN];
    #pragma unroll
    for (int i = 0; i < TM; i++)
        #pragma unroll
        for (int j = 0; j < TN; j++) acc[i][j] = 0.f;

    const int T = K / BK;

    auto issue_stage = [&](int stage, int buf) {
        const int k0 = stage * BK;
        #pragma unroll
        for (int v = 0; v < XE; v++) {
            int t2 = tid + v*TPB;
            int kq = t2 % BK, r = t2 / BK;
            cp4(xb[buf] + (uint32_t)((kq*BMP + r) * 4),
                &X[(size_t)(row0 + r) * ldx + k0 + kq]);
        }
        #pragma unroll
        for (int v = 0; v < WE; v++) {
            int t2 = tid + v*TPB;
            int kq = t2 % BK, r = t2 / BK;
            cp4(wb[buf] + (uint32_t)((kq*BNP + r) * 4),
                &W[(size_t)(col0 + r) * ldw + k0 + kq]);
        }
        cp_commit();
    };

    issue_stage(0, 0);
    if (T > 1) issue_stage(1, 1);

    for (int t = 0; t < T; t++) {
        if (t + 1 < T) cp_wait<1>(); else cp_wait<0>();
        __syncthreads();
        const int buf = t & 1;
        #pragma unroll
        for (int kk = 0; kk < BK; kk++) {
            float xm[TM], wn[TN];
            #pragma unroll
            for (int i = 0; i < TM; i += 4)
                *(float4*)&xm[i] = *(const float4*)&Xs[buf][kk][ty*TM + i];
            #pragma unroll
            for (int j = 0; j < TN; j += 4)
                *(float4*)&wn[j] = *(const float4*)&Ws[buf][kk][tx*TN + j];
            #pragma unroll
            for (int i = 0; i < TM; i++)
                #pragma unroll
                for (int j = 0; j < TN; j++)
                    acc[i][j] = fmaf(xm[i], wn[j], acc[i][j]);
        }
        __syncthreads();
        if (t + 2 < T) issue_stage(t + 2, buf);
    }

    #pragma unroll
    for (int i = 0; i < TM; i++) {
        int row = row0 + ty*TM + i;
        float s0 = 0.f, s1 = 0.f;
        if (MODE == 2) {
            s0 = (g_l1b[row] - g_stats[0]) / g_stats[1];
            s1 = (g_l1c[row] - g_stats[2]) / g_stats[3];
        }
        #pragma unroll
        for (int jj = 0; jj < TN; jj += 4) {
            int col = col0 + tx*TN + jj;
            float4 o;
            float* ov = (float*)&o;
            #pragma unroll
            for (int q = 0; q < 4; q++) {
                float v = acc[i][jj + q];
                if (MODE == 2) {
                    int cq = col + q;
                    v += s0 * Wih[cq*2 + 0] + s1 * Wih[cq*2 + 1]
                       + bih[cq] + bhh[cq];
                }
                ov[q] = v;
            }
            *(float4*)&C[(size_t)row * ldc + col] = o;
        }
    }
}

// ---------------- stats (mean + ddof=1 std), double accumulation ----------------
__global__ void stats_kernel(const float* __restrict__ l1b,
                             const float* __restrict__ l1c,
                             float* __restrict__ stats) {
    int tid = threadIdx.x;
    double sb = 0, sb2 = 0, sc = 0, sc2 = 0;
    for (int i = tid; i < B_SZ; i += 256) {
        double v = (double)l1b[i]; sb += v; sb2 += v*v;
        double w = (double)l1c[i]; sc += w; sc2 += w*w;
    }
    __shared__ double red[256];
    auto reduce = [&](double v) -> double {
        red[tid] = v; __syncthreads();
        for (int o = 128; o > 0; o >>= 1) {
            if (tid < o) red[tid] += red[tid + o];
            __syncthreads();
        }
        double r = red[0]; __syncthreads();
        return r;
    };
    double Sb = reduce(sb), Sb2 = reduce(sb2), Sc = reduce(sc), Sc2 = reduce(sc2);
    if (tid == 0) {
        double nb = (double)B_SZ;
        double mb = Sb / nb, mc = Sc / nb;
        double vb = (Sb2 - Sb*Sb/nb) / (nb - 1.0);
        double vc = (Sc2 - Sc*Sc/nb) / (nb - 1.0);
        stats[0] = (float)mb; stats[1] = (float)sqrt(vb);
        stats[2] = (float)mc; stats[3] = (float)sqrt(vc);
    }
}

// ---------------- LSTM pointwise + output head ----------------
#define ROWS_PER 2
__global__ void lstm_update(const float* __restrict__ gates,
                            const float* __restrict__ Wlll, const float* __restrict__ blll,
                            const float* __restrict__ Wlin, const float* __restrict__ blin,
                            float* __restrict__ hidden, float* __restrict__ cell,
                            float* __restrict__ gamma, float* __restrict__ theta)
{
    int j = threadIdx.x;   // 0..127
    int base = blockIdx.x * ROWS_PER;
    __shared__ float c2sh[DIM_SZ];
    __shared__ float r0[DIM_SZ], r1[DIM_SZ];
    for (int r = 0; r < ROWS_PER; r++) {
        int bi = base + r;
        const float* g = gates + (size_t)bi * GATE_SZ;
        float gi = g[j], gf = g[DIM_SZ + j], gg = g[2*DIM_SZ + j], go = g[3*DIM_SZ + j];
        float cprev = cell[(size_t)bi * DIM_SZ + j];
        float ii = 1.f / (1.f + expf(-gi));
        float ff = 1.f / (1.f + expf(-gf));
        float oo = 1.f / (1.f + expf(-go));
        float c2 = ff * cprev + ii * tanhf(gg);
        float h2 = oo * tanhf(c2);
        cell[(size_t)bi * DIM_SZ + j] = c2;
        hidden[(size_t)bi * DIM_SZ + j] = h2;
        c2sh[j] = c2;
        __syncthreads();
        float acc = blll[j];
        #pragma unroll 8
        for (int k = 0; k < DIM_SZ; k++)
            acc = fmaf(c2sh[k], __ldg(&Wlll[j * DIM_SZ + k]), acc);
        float t = fmaxf(acc, 0.f);
        r0[j] = t * Wlin[j];
        r1[j] = t * Wlin[DIM_SZ + j];
        __syncthreads();
        for (int o = 64; o > 0; o >>= 1) {
            if (j < o) { r0[j] += r0[j + o]; r1[j] += r1[j + o]; }
            __syncthreads();
        }
        if (j == 0) {
            float a0 = r0[0] + blin[0], a1 = r1[0] + blin[1];
            gamma[bi] = fmaxf(a0, 0.f) + log1pf(expf(-fabsf(a0)));
            theta[bi] = fmaxf(a1, 0.f) + log1pf(expf(-fabsf(a1)));
        }
        __syncthreads();
    }
}

// ---------------- soft-threshold with top-p keep (radix select on |d| bits) ----
__global__ void threshold_kernel(const float* __restrict__ c, float* __restrict__ x,
                                 float* __restrict__ xhi, float* __restrict__ xlo,
                                 const float* __restrict__ gamma,
                                 const float* __restrict__ theta, int p)
{
    int bi = blockIdx.x;
    int tid = threadIdx.x;   // 256 threads, 8 elems each
    float gm = gamma[bi], th = theta[bi];
    const float* crow = c + (size_t)bi * N_SZ;
    float* xrow = x + (size_t)bi * N_SZ;
    float* hrow = xhi + (size_t)bi * N_SZ;
    float* lrow = xlo + (size_t)bi * N_SZ;

    float dv[8]; unsigned ab[8];
    #pragma unroll
    for (int e = 0; e < 8; e++) {
        int idx = tid + e * 256;
        float d = fmaf(gm, crow[idx], xrow[idx]);
        dv[e] = d;
        ab[e] = __float_as_uint(fabsf(d));
    }

    __shared__ int hist[256];
    __shared__ unsigned sh_pref;
    __shared__ int sh_k;
    unsigned prefix = 0; int k = p;

    for (int pass = 0; pass < 4; pass++) {
        int shift = 24 - 8 * pass;
        hist[tid] = 0;
        __syncthreads();
        #pragma unroll
        for (int e = 0; e < 8; e++) {
            if ((unsigned)(((unsigned long long)ab[e]) >> (shift + 8)) == prefix)
                atomicAdd(&hist[(ab[e] >> shift) & 255], 1);
        }
        __syncthreads();
        if (tid == 0) {
            int cum = 0, bsel = 0;
            for (int b = 255; b >= 0; b--) {
                cum += hist[b];
                if (cum >= k) { bsel = b; break; }
            }
            k -= (cum - hist[bsel]);
            prefix = (prefix << 8) | (unsigned)bsel;
            sh_pref = prefix; sh_k = k;
        }
        __syncthreads();
        prefix = sh_pref; k = sh_k;
        __syncthreads();
    }

    float thresh = __uint_as_float(prefix);
    #pragma unroll
    for (int e = 0; e < 8; e++) {
        int idx = tid + e * 256;
        float d = dv[e], ad = fabsf(d);
        float soft = copysignf(fmaxf(ad - th, 0.f), d);
        float val = (ad > thresh) ? d : soft;
        xrow[idx] = val;
        float h = to_tf32(val);
        hrow[idx] = h;
        lrow[idx] = val - h;
    }
}

// ---------------- host driver (graph-capturable) ----------------
extern "C" void kernel_launch(void* const* d_in, const int* in_sizes, int n_in,
                              void* d_out, int out_size)
{
    const float* y     = (const float*)d_in[0];
    const float* A     = (const float*)d_in[1];
    const float* W_ih  = (const float*)d_in[2];
    const float* W_hh  = (const float*)d_in[3];
    const float* b_ih  = (const float*)d_in[4];
    const float* b_hh  = (const float*)d_in[5];
    const float* W_lll = (const float*)d_in[6];
    const float* b_lll = (const float*)d_in[7];
    const float* W_lin = (const float*)d_in[8];
    const float* b_lin = (const float*)d_in[9];
    const float* h0    = (const float*)d_in[10];
    const float* c0    = (const float*)d_in[11];
    float* x = (float*)d_out;

    float *Ahi, *Alo, *Athi, *Atlo, *bhi, *blo, *xhi, *xlo, *cc, *part;
    float *gates, *hid, *cel, *l1b, *l1c, *gam, *the, *stats;
    cudaGetSymbolAddress((void**)&Ahi,  g_Ahi);
    cudaGetSymbolAddress((void**)&Alo,  g_Alo);
    cudaGetSymbolAddress((void**)&Athi, g_Athi);
    cudaGetSymbolAddress((void**)&Atlo, g_Atlo);
    cudaGetSymbolAddress((void**)&bhi,  g_bhi);
    cudaGetSymbolAddress((void**)&blo,  g_blo);
    cudaGetSymbolAddress((void**)&xhi,  g_xhi);
    cudaGetSymbolAddress((void**)&xlo,  g_xlo);
    cudaGetSymbolAddress((void**)&cc,   g_c);
    cudaGetSymbolAddress((void**)&part, g_part);
    cudaGetSymbolAddress((void**)&gates, g_gates);
    cudaGetSymbolAddress((void**)&hid,  g_hidden);
    cudaGetSymbolAddress((void**)&cel,  g_cell);
    cudaGetSymbolAddress((void**)&l1b,  g_l1b);
    cudaGetSymbolAddress((void**)&l1c,  g_l1c);
    cudaGetSymbolAddress((void**)&gam,  g_gamma);
    cudaGetSymbolAddress((void**)&the,  g_theta);
    cudaGetSymbolAddress((void**)&stats, g_stats);

    // dynamic smem (bytes): stage = (2*BM*20 + 2*BN*20) floats, double-buffered
    constexpr int SMEM1 = 2 * (2 * 128 * 20 + 2 * 64  * 20) * 4;   // 61440 B (128x64)
    constexpr int SMEM2 = 2 * (2 * 128 * 20 + 2 * 128 * 20) * 4;   // 81920 B (128x128)
    cudaFuncSetAttribute((const void*)gemm_mma<128, 64, 4, 2, N_SZ / SPLITK, 2>,
                         cudaFuncAttributeMaxDynamicSharedMemorySize, SMEM1);
    cudaFuncSetAttribute((const void*)gemm_mma<128, 128, 4, 2, M_SZ, 0>,
                         cudaFuncAttributeMaxDynamicSharedMemorySize, SMEM2);

    cudaMemsetAsync(x, 0, sizeof(float) * (size_t)B_SZ * N_SZ, 0);
    split_A<<<dim3(N_SZ/32, M_SZ/32), dim3(32, 8)>>>(A, Ahi, Alo, Athi, Atlo);
    init_hc<<<(B_SZ*DIM_SZ + 255)/256, 256>>>(h0, c0, hid, cel);

    // s_sched = clip(linspace(S/K, S*1.4, K), 0, S*1.2).astype(int32)
    static const int sched[K_ITERS] = {6, 15, 24, 33, 41, 50, 59, 68,
                                       77, 86, 95, 104, 113, 120, 120, 120};

    for (int it = 0; it < K_ITERS; ++it) {
        if (it == 0) {
            split_y<<<B_SZ, 128>>>(y, bhi, blo, l1b, l1c);   // b = y; l1b; zero l1c
        } else {
            // partials = x@A^T over K halves: 128x64 tiles, grid (8,16,2) = 256 CTAs
            gemm_mma<128, 64, 4, 2, N_SZ / SPLITK, 2>
                <<<dim3(M_SZ/64, B_SZ/128, SPLITK), 256, SMEM1>>>(
                xhi, xlo, Ahi, Alo, N_SZ, part, nullptr, M_SZ);
            // b = y - sum partials; hi/lo split; l1b direct; zero l1c
            finalize_b<<<B_SZ, 128>>>(y, part, bhi, blo, l1b, l1c);
        }

        // c = b @ A  (rows=B, cols=N, K=M); 128x128 tiles -> 256 CTAs
        gemm_mma<128, 128, 4, 2, M_SZ, 0><<<dim3(N_SZ/128, B_SZ/128), 256, SMEM2>>>(
            bhi, blo, Athi, Atlo, M_SZ, cc, l1c, N_SZ);

        if (it == 0) stats_kernel<<<1, 256>>>(l1b, l1c, stats);

        // gates = stack @ W_ih^T + b_ih + hidden @ W_hh^T + b_hh
        gemm_cp<64,64,16,4,4,2,0><<<dim3(GATE_SZ/64, B_SZ/64), 256>>>(
            hid, DIM_SZ, W_hh, DIM_SZ, DIM_SZ, nullptr, W_ih, b_ih, b_hh, gates, GATE_SZ, nullptr);

        lstm_update<<<B_SZ/ROWS_PER, DIM_SZ>>>(gates, W_lll, b_lll, W_lin, b_lin,
                                               hid, cel, gam, the);

        // d = x + gamma*c; x = top-p-aware soft threshold; split x -> hi/lo
        threshold_kernel<<<B_SZ, 256>>>(cc, x, xhi, xlo, gam, the, sched[it]);
    }
}

// round 16
// speedup vs baseline: 1.1142x; 1.0733x over previous
#include <cuda_runtime.h>
#include <stdint.h>
#include <math.h>

#define B_SZ 2048
#define M_SZ 512
#define N_SZ 2048
#define DIM_SZ 128
#define GATE_SZ 512
#define K_ITERS 16
#define SPLITK 2

// ---------------- scratch (static device globals; no allocation) ----------------
__device__ float g_Ahi[(size_t)M_SZ * N_SZ];
__device__ float g_Alo[(size_t)M_SZ * N_SZ];
__device__ float g_Athi[(size_t)N_SZ * M_SZ];
__device__ float g_Atlo[(size_t)N_SZ * M_SZ];
__device__ float g_bhi[(size_t)B_SZ * M_SZ];
__device__ float g_blo[(size_t)B_SZ * M_SZ];
__device__ float g_xhi[(size_t)B_SZ * N_SZ];
__device__ float g_xlo[(size_t)B_SZ * N_SZ];
__device__ float g_c[(size_t)B_SZ * N_SZ];
__device__ float g_part[SPLITK][(size_t)B_SZ * M_SZ];   // split-K partials for GEMM1
__device__ float g_gates[(size_t)B_SZ * GATE_SZ];
__device__ float g_hidden[(size_t)B_SZ * DIM_SZ];
__device__ float g_cell[(size_t)B_SZ * DIM_SZ];
__device__ float g_l1b[B_SZ];
__device__ float g_l1c[B_SZ];
__device__ float g_gamma[B_SZ];
__device__ float g_theta[B_SZ];
__device__ float g_stats[4];   // mean_b, std_b, mean_c, std_c

// ---------------- PTX helpers (all sm_80-level; compile at compute_100) --------
__device__ __forceinline__ uint32_t smem_u32(const void* p) {
    uint32_t a;
    asm("{ .reg .u64 t; cvta.to.shared.u64 t, %1; cvt.u32.u64 %0, t; }" : "=r"(a) : "l"(p));
    return a;
}
__device__ __forceinline__ float to_tf32(float x) {
    uint32_t r;
    asm("cvt.rna.tf32.f32 %0, %1;" : "=r"(r) : "f"(x));
    return __uint_as_float(r);
}
__device__ __forceinline__ void cp16(uint32_t dst, const void* src) {
    asm volatile("cp.async.cg.shared.global [%0], [%1], 16;\n" :: "r"(dst), "l"(src));
}
__device__ __forceinline__ void cp4(uint32_t dst, const float* src) {
    asm volatile("cp.async.ca.shared.global [%0], [%1], 4;\n" :: "r"(dst), "l"(src));
}
__device__ __forceinline__ void cp_commit() {
    asm volatile("cp.async.commit_group;\n" ::: "memory");
}
template<int N>
__device__ __forceinline__ void cp_wait() {
    asm volatile("cp.async.wait_group %0;\n" :: "n"(N) : "memory");
}
// m16n8k8 tf32 MMA, D += A*B (A row-major 16x8, B col-major 8x8)
__device__ __forceinline__ void mma_tf32(float* d, const uint32_t* a, const uint32_t* b) {
    asm volatile(
        "mma.sync.aligned.m16n8k8.row.col.f32.tf32.tf32.f32 "
        "{%0,%1,%2,%3}, {%4,%5,%6,%7}, {%8,%9}, {%0,%1,%2,%3};"
        : "+f"(d[0]), "+f"(d[1]), "+f"(d[2]), "+f"(d[3])
        : "r"(a[0]), "r"(a[1]), "r"(a[2]), "r"(a[3]), "r"(b[0]), "r"(b[1]));
}

// ============================================================================
// 3xTF32 NT GEMM via mma.sync: C[r,c] = sum_k X[r,k]*W[c,k], X=Xhi+Xlo etc.
// CTA: 256 threads = WM x WN warps; tile BM x BN, BK=16, cp.async double buffer.
// KLEN = K handled by this CTA; ldk = row stride of X/W; koff = blockIdx.z*KLEN.
// MODE 0: Cout = acc; fused L1 row sums (atomic)
// MODE 2: Cout(+ z offset) = acc partial; NO l1 (split-K partial pass)
// ============================================================================
template<int BM, int BN, int WM, int WN, int KLEN, int MODE>
__global__ __launch_bounds__(256, 2)
void gemm_mma(const float* __restrict__ Xhi, const float* __restrict__ Xlo,
              const float* __restrict__ Whi, const float* __restrict__ Wlo,
              int ldk,
              float* __restrict__ Cout,
              float* __restrict__ l1out, int ldo)
{
    static_assert(WM * WN == 8, "8 warps");
    constexpr int BK = 16;
    constexpr int ST = BK + 4;            // row stride in floats (20) -> conflict-free
    constexpr int SZA = BM * ST;          // floats per A part
    constexpr int SZB = BN * ST;
    constexpr int STAGEF = 2 * SZA + 2 * SZB;
    constexpr int T = KLEN / BK;
    constexpr int WTM = BM / WM;          // warp tile m (32)
    constexpr int WTN = BN / WN;          // warp tile n
    constexpr int MT  = WTM / 16;         // m-tiles per warp (2)
    constexpr int NTN = WTN / 8;          // n-tiles per warp

    extern __shared__ float sm[];

    const int tid = threadIdx.x;
    const int wid = tid >> 5;
    const int lane = tid & 31;
    const int wm = wid / WN;
    const int wn = wid % WN;
    const int ar = lane >> 2;             // 0..7
    const int ak = lane & 3;              // 0..3
    const int row0 = blockIdx.y * BM;
    const int col0 = blockIdx.x * BN;
    const int koff = blockIdx.z * KLEN;
    float* outp = (MODE == 2) ? Cout + (size_t)blockIdx.z * B_SZ * M_SZ : Cout;

    float acc[MT][NTN][4];
    #pragma unroll
    for (int mt = 0; mt < MT; mt++)
        #pragma unroll
        for (int nt = 0; nt < NTN; nt++)
            #pragma unroll
            for (int q = 0; q < 4; q++) acc[mt][nt][q] = 0.f;

    auto load_stage = [&](int t, int buf) {
        float* s = sm + buf * STAGEF;
        const int k0 = koff + t * BK;
        #pragma unroll
        for (int c = tid; c < BM * 4; c += 256) {
            int r = c >> 2, kc = c & 3;
            const size_t src = (size_t)(row0 + r) * ldk + k0 + kc * 4;
            cp16(smem_u32(s + r * ST + kc * 4), &Xhi[src]);
            cp16(smem_u32(s + SZA + r * ST + kc * 4), &Xlo[src]);
        }
        #pragma unroll
        for (int c = tid; c < BN * 4; c += 256) {
            int r = c >> 2, kc = c & 3;
            const size_t src = (size_t)(col0 + r) * ldk + k0 + kc * 4;
            cp16(smem_u32(s + 2 * SZA + r * ST + kc * 4), &Whi[src]);
            cp16(smem_u32(s + 2 * SZA + SZB + r * ST + kc * 4), &Wlo[src]);
        }
        cp_commit();
    };

    load_stage(0, 0);
    if (T > 1) load_stage(1, 1);

    for (int t = 0; t < T; t++) {
        if (t + 1 < T) cp_wait<1>(); else cp_wait<0>();
        __syncthreads();
        const float* s = sm + (t & 1) * STAGEF;
        const float* As_hi = s;
        const float* As_lo = s + SZA;
        const float* Bs_hi = s + 2 * SZA;
        const float* Bs_lo = s + 2 * SZA + SZB;

        #pragma unroll
        for (int ks = 0; ks < 2; ks++) {
            const int kk = ks * 8;
            uint32_t ahi[MT][4], alo[MT][4];
            #pragma unroll
            for (int mt = 0; mt < MT; mt++) {
                const float* pa = As_hi + (wm * WTM + mt * 16 + ar) * ST + kk + ak;
                ahi[mt][0] = __float_as_uint(pa[0]);
                ahi[mt][1] = __float_as_uint(pa[8 * ST]);
                ahi[mt][2] = __float_as_uint(pa[4]);
                ahi[mt][3] = __float_as_uint(pa[8 * ST + 4]);
                const float* pl = As_lo + (wm * WTM + mt * 16 + ar) * ST + kk + ak;
                alo[mt][0] = __float_as_uint(pl[0]);
                alo[mt][1] = __float_as_uint(pl[8 * ST]);
                alo[mt][2] = __float_as_uint(pl[4]);
                alo[mt][3] = __float_as_uint(pl[8 * ST + 4]);
            }
            #pragma unroll
            for (int nt = 0; nt < NTN; nt++) {
                uint32_t bhi[2], blo[2];
                const float* pb = Bs_hi + (wn * WTN + nt * 8 + ar) * ST + kk + ak;
                bhi[0] = __float_as_uint(pb[0]);
                bhi[1] = __float_as_uint(pb[4]);
                const float* pc = Bs_lo + (wn * WTN + nt * 8 + ar) * ST + kk + ak;
                blo[0] = __float_as_uint(pc[0]);
                blo[1] = __float_as_uint(pc[4]);
                #pragma unroll
                for (int mt = 0; mt < MT; mt++) {
                    mma_tf32(acc[mt][nt], ahi[mt], bhi);
                    mma_tf32(acc[mt][nt], ahi[mt], blo);
                    mma_tf32(acc[mt][nt], alo[mt], bhi);
                }
            }
        }
        __syncthreads();
        if (t + 2 < T) load_stage(t + 2, t & 1);
    }

    // ---------------- epilogue ----------------
    float rs[MT * 2];
    #pragma unroll
    for (int i = 0; i < MT * 2; i++) rs[i] = 0.f;
    #pragma unroll
    for (int mt = 0; mt < MT; mt++) {
        const int gr0 = row0 + wm * WTM + mt * 16 + ar;
        const int gr1 = gr0 + 8;
        #pragma unroll
        for (int nt = 0; nt < NTN; nt++) {
            const int gc = col0 + wn * WTN + nt * 8 + ak * 2;
            float v0 = acc[mt][nt][0], v1 = acc[mt][nt][1];
            float v2 = acc[mt][nt][2], v3 = acc[mt][nt][3];
            const size_t o0 = (size_t)gr0 * ldo + gc;
            const size_t o1 = (size_t)gr1 * ldo + gc;
            *(float2*)&outp[o0] = make_float2(v0, v1);
            *(float2*)&outp[o1] = make_float2(v2, v3);
            if (MODE == 0) {
                rs[mt * 2 + 0] += fabsf(v0) + fabsf(v1);
                rs[mt * 2 + 1] += fabsf(v2) + fabsf(v3);
            }
        }
    }
    if (MODE == 0) {
        #pragma unroll
        for (int i = 0; i < MT * 2; i++) {
            rs[i] += __shfl_xor_sync(0xffffffffu, rs[i], 1);
            rs[i] += __shfl_xor_sync(0xffffffffu, rs[i], 2);
        }
        if (ak == 0) {
            #pragma unroll
            for (int i = 0; i < MT * 2; i++) {
                int r = row0 + wm * WTM + (i >> 1) * 16 + (i & 1) * 8 + ar;
                atomicAdd(&l1out[r], rs[i]);
            }
        }
    }
}

// ---------------- finalize b = y - sum(partials); hi/lo split; l1b (direct) ----
// Also zeroes l1c[row] ahead of GEMM2's atomics (same-stream ordering).
__global__ void finalize_b(const float* __restrict__ y,
                           const float* __restrict__ parts,
                           float* __restrict__ bhi, float* __restrict__ blo,
                           float* __restrict__ l1b, float* __restrict__ l1c) {
    int row = blockIdx.x;
    int tid = threadIdx.x;   // 128 threads, 4 elems each
    const size_t base = (size_t)row * M_SZ + tid * 4;
    float4 yv = *(const float4*)&y[base];
    float v0 = yv.x, v1 = yv.y, v2 = yv.z, v3 = yv.w;
    #pragma unroll
    for (int z = 0; z < SPLITK; z++) {
        float4 p = *(const float4*)&parts[(size_t)z * B_SZ * M_SZ + base];
        v0 -= p.x; v1 -= p.y; v2 -= p.z; v3 -= p.w;
    }
    float h0 = to_tf32(v0), h1 = to_tf32(v1), h2 = to_tf32(v2), h3 = to_tf32(v3);
    *(float4*)&bhi[base] = make_float4(h0, h1, h2, h3);
    *(float4*)&blo[base] = make_float4(v0 - h0, v1 - h1, v2 - h2, v3 - h3);
    float s = fabsf(v0) + fabsf(v1) + fabsf(v2) + fabsf(v3);
    __shared__ float red[128];
    red[tid] = s; __syncthreads();
    for (int o = 64; o > 0; o >>= 1) {
        if (tid < o) red[tid] += red[tid + o];
        __syncthreads();
    }
    if (tid == 0) { l1b[row] = red[0]; l1c[row] = 0.f; }
}

// ---------------- prologue: split A into hi/lo + transposed hi/lo ----------------
__global__ void split_A(const float* __restrict__ A,
                        float* __restrict__ Ahi, float* __restrict__ Alo,
                        float* __restrict__ Athi, float* __restrict__ Atlo) {
    __shared__ float th[32][33], tl[32][33];
    int n0 = blockIdx.x * 32, m0 = blockIdx.y * 32;
    int tx = threadIdx.x, ty = threadIdx.y;   // block (32, 8)
    #pragma unroll
    for (int i = 0; i < 32; i += 8) {
        size_t idx = (size_t)(m0 + ty + i) * N_SZ + n0 + tx;
        float a = A[idx];
        float h = to_tf32(a), l = a - h;
        Ahi[idx] = h; Alo[idx] = l;
        th[ty + i][tx] = h; tl[ty + i][tx] = l;
    }
    __syncthreads();
    #pragma unroll
    for (int i = 0; i < 32; i += 8) {
        size_t idx = (size_t)(n0 + ty + i) * M_SZ + m0 + tx;
        Athi[idx] = th[tx][ty + i];
        Atlo[idx] = tl[tx][ty + i];
    }
}

// ---------------- iter 0: b = y; hi/lo split + l1b; zero l1c ----------------
__global__ void split_y(const float* __restrict__ y,
                        float* __restrict__ bhi, float* __restrict__ blo,
                        float* __restrict__ l1b, float* __restrict__ l1c) {
    int row = blockIdx.x;
    int tid = threadIdx.x;   // 128
    const float* p = y + (size_t)row * M_SZ;
    float4 v = *(const float4*)&p[tid * 4];
    float h0 = to_tf32(v.x), h1 = to_tf32(v.y), h2 = to_tf32(v.z), h3 = to_tf32(v.w);
    *(float4*)&bhi[(size_t)row * M_SZ + tid * 4] = make_float4(h0, h1, h2, h3);
    *(float4*)&blo[(size_t)row * M_SZ + tid * 4] = make_float4(v.x - h0, v.y - h1, v.z - h2, v.w - h3);
    float s = fabsf(v.x) + fabsf(v.y) + fabsf(v.z) + fabsf(v.w);
    __shared__ float red[128];
    red[tid] = s; __syncthreads();
    for (int o = 64; o > 0; o >>= 1) {
        if (tid < o) red[tid] += red[tid + o];
        __syncthreads();
    }
    if (tid == 0) { l1b[row] = red[0]; l1c[row] = 0.f; }
}

// ---------------- init hidden/cell from h0/c0 ----------------
__global__ void init_hc(const float* __restrict__ h0, const float* __restrict__ c0,
                        float* __restrict__ hidden, float* __restrict__ cell) {
    int idx = blockIdx.x * blockDim.x + threadIdx.x;
    if (idx < B_SZ * DIM_SZ) {
        int j = idx & (DIM_SZ - 1);
        hidden[idx] = h0[j];
        cell[idx] = c0[j];
    }
}

// ---------------- SIMT NT GEMM (LSTM gates only) ----------------
// MODE 2: C = acc + s0*Wih[c,0]+s1*Wih[c,1]+bih[c]+bhh[c]
template<int BM, int BN, int BK, int TM, int TN, int MODE, int FUSE_L1>
__global__ __launch_bounds__((BM/TM)*(BN/TN), 2)
void gemm_cp(const float* __restrict__ X, int ldx,
             const float* __restrict__ W, int ldw,
             int K,
             const float* __restrict__ Yin,
             const float* __restrict__ Wih,
             const float* __restrict__ bih,
             const float* __restrict__ bhh,
             float* __restrict__ C, int ldc,
             float* __restrict__ l1out)
{
    constexpr int TPB = (BM/TM)*(BN/TN);
    constexpr int BMP = BM + 4;
    constexpr int BNP = BN + 4;
    constexpr int XE = BM*BK/TPB;
    constexpr int WE = BN*BK/TPB;

    __shared__ float Xs[2][BK][BMP];
    __shared__ float Ws[2][BK][BNP];

    const int tid = threadIdx.x;
    const int tx = tid % (BN/TN);
    const int ty = tid / (BN/TN);
    const int row0 = blockIdx.y * BM;
    const int col0 = blockIdx.x * BN;

    uint32_t xb[2], wb[2];
    xb[0] = smem_u32(&Xs[0][0][0]); xb[1] = smem_u32(&Xs[1][0][0]);
    wb[0] = smem_u32(&Ws[0][0][0]); wb[1] = smem_u32(&Ws[1][0][0]);

    float acc[TM][TN];
    #pragma unroll
    for (int i = 0; i < TM; i++)
        #pragma unroll
        for (int j = 0; j < TN; j++) acc[i][j] = 0.f;

    const int T = K / BK;

    auto issue_stage = [&](int stage, int buf) {
        const int k0 = stage * BK;
        #pragma unroll
        for (int v = 0; v < XE; v++) {
            int t2 = tid + v*TPB;
            int kq = t2 % BK, r = t2 / BK;
            cp4(xb[buf] + (uint32_t)((kq*BMP + r) * 4),
                &X[(size_t)(row0 + r) * ldx + k0 + kq]);
        }
        #pragma unroll
        for (int v = 0; v < WE; v++) {
            int t2 = tid + v*TPB;
            int kq = t2 % BK, r = t2 / BK;
            cp4(wb[buf] + (uint32_t)((kq*BNP + r) * 4),
                &W[(size_t)(col0 + r) * ldw + k0 + kq]);
        }
        cp_commit();
    };

    issue_stage(0, 0);
    if (T > 1) issue_stage(1, 1);

    for (int t = 0; t < T; t++) {
        if (t + 1 < T) cp_wait<1>(); else cp_wait<0>();
        __syncthreads();
        const int buf = t & 1;
        #pragma unroll
        for (int kk = 0; kk < BK; kk++) {
            float xm[TM], wn[TN];
            #pragma unroll
            for (int i = 0; i < TM; i += 4)
                *(float4*)&xm[i] = *(const float4*)&Xs[buf][kk][ty*TM + i];
            #pragma unroll
            for (int j = 0; j < TN; j += 4)
                *(float4*)&wn[j] = *(const float4*)&Ws[buf][kk][tx*TN + j];
            #pragma unroll
            for (int i = 0; i < TM; i++)
                #pragma unroll
                for (int j = 0; j < TN; j++)
                    acc[i][j] = fmaf(xm[i], wn[j], acc[i][j]);
        }
        __syncthreads();
        if (t + 2 < T) issue_stage(t + 2, buf);
    }

    #pragma unroll
    for (int i = 0; i < TM; i++) {
        int row = row0 + ty*TM + i;
        float s0 = 0.f, s1 = 0.f;
        if (MODE == 2) {
            s0 = (g_l1b[row] - g_stats[0]) / g_stats[1];
            s1 = (g_l1c[row] - g_stats[2]) / g_stats[3];
        }
        #pragma unroll
        for (int jj = 0; jj < TN; jj += 4) {
            int col = col0 + tx*TN + jj;
            float4 o;
            float* ov = (float*)&o;
            #pragma unroll
            for (int q = 0; q < 4; q++) {
                float v = acc[i][jj + q];
                if (MODE == 2) {
                    int cq = col + q;
                    v += s0 * Wih[cq*2 + 0] + s1 * Wih[cq*2 + 1]
                       + bih[cq] + bhh[cq];
                }
                ov[q] = v;
            }
            *(float4*)&C[(size_t)row * ldc + col] = o;
        }
    }
}

// ---------------- stats (mean + ddof=1 std), double accumulation ----------------
__global__ void stats_kernel(const float* __restrict__ l1b,
                             const float* __restrict__ l1c,
                             float* __restrict__ stats) {
    int tid = threadIdx.x;
    double sb = 0, sb2 = 0, sc = 0, sc2 = 0;
    for (int i = tid; i < B_SZ; i += 256) {
        double v = (double)l1b[i]; sb += v; sb2 += v*v;
        double w = (double)l1c[i]; sc += w; sc2 += w*w;
    }
    __shared__ double red[256];
    auto reduce = [&](double v) -> double {
        red[tid] = v; __syncthreads();
        for (int o = 128; o > 0; o >>= 1) {
            if (tid < o) red[tid] += red[tid + o];
            __syncthreads();
        }
        double r = red[0]; __syncthreads();
        return r;
    };
    double Sb = reduce(sb), Sb2 = reduce(sb2), Sc = reduce(sc), Sc2 = reduce(sc2);
    if (tid == 0) {
        double nb = (double)B_SZ;
        double mb = Sb / nb, mc = Sc / nb;
        double vb = (Sb2 - Sb*Sb/nb) / (nb - 1.0);
        double vc = (Sc2 - Sc*Sc/nb) / (nb - 1.0);
        stats[0] = (float)mb; stats[1] = (float)sqrt(vb);
        stats[2] = (float)mc; stats[3] = (float)sqrt(vc);
    }
}

// ---------------- LSTM pointwise + output head ----------------
#define ROWS_PER 2
__global__ void lstm_update(const float* __restrict__ gates,
                            const float* __restrict__ Wlll, const float* __restrict__ blll,
                            const float* __restrict__ Wlin, const float* __restrict__ blin,
                            float* __restrict__ hidden, float* __restrict__ cell,
                            float* __restrict__ gamma, float* __restrict__ theta)
{
    int j = threadIdx.x;   // 0..127
    int base = blockIdx.x * ROWS_PER;
    __shared__ float c2sh[DIM_SZ];
    __shared__ float r0[DIM_SZ], r1[DIM_SZ];
    for (int r = 0; r < ROWS_PER; r++) {
        int bi = base + r;
        const float* g = gates + (size_t)bi * GATE_SZ;
        float gi = g[j], gf = g[DIM_SZ + j], gg = g[2*DIM_SZ + j], go = g[3*DIM_SZ + j];
        float cprev = cell[(size_t)bi * DIM_SZ + j];
        float ii = 1.f / (1.f + expf(-gi));
        float ff = 1.f / (1.f + expf(-gf));
        float oo = 1.f / (1.f + expf(-go));
        float c2 = ff * cprev + ii * tanhf(gg);
        float h2 = oo * tanhf(c2);
        cell[(size_t)bi * DIM_SZ + j] = c2;
        hidden[(size_t)bi * DIM_SZ + j] = h2;
        c2sh[j] = c2;
        __syncthreads();
        float acc = blll[j];
        #pragma unroll 8
        for (int k = 0; k < DIM_SZ; k++)
            acc = fmaf(c2sh[k], __ldg(&Wlll[j * DIM_SZ + k]), acc);
        float t = fmaxf(acc, 0.f);
        r0[j] = t * Wlin[j];
        r1[j] = t * Wlin[DIM_SZ + j];
        __syncthreads();
        for (int o = 64; o > 0; o >>= 1) {
            if (j < o) { r0[j] += r0[j + o]; r1[j] += r1[j + o]; }
            __syncthreads();
        }
        if (j == 0) {
            float a0 = r0[0] + blin[0], a1 = r1[0] + blin[1];
            gamma[bi] = fmaxf(a0, 0.f) + log1pf(expf(-fabsf(a0)));
            theta[bi] = fmaxf(a1, 0.f) + log1pf(expf(-fabsf(a1)));
        }
        __syncthreads();
    }
}

// ---------------- soft-threshold with top-p keep (radix select on |d| bits) ----
// Per-warp histograms (8 copies) kill same-bin shared-atomic serialization;
// parallel suffix scan replaces the thread-0 serial 256-bin walk. The selected
// bin and k recurrence are identical to the serial version (bitwise-same x).
__global__ void threshold_kernel(const float* __restrict__ c, float* __restrict__ x,
                                 float* __restrict__ xhi, float* __restrict__ xlo,
                                 const float* __restrict__ gamma,
                                 const float* __restrict__ theta, int p)
{
    int bi = blockIdx.x;
    int tid = threadIdx.x;   // 256 threads, 8 elems each
    int warp = tid >> 5;
    float gm = gamma[bi], th = theta[bi];
    const float* crow = c + (size_t)bi * N_SZ;
    float* xrow = x + (size_t)bi * N_SZ;
    float* hrow = xhi + (size_t)bi * N_SZ;
    float* lrow = xlo + (size_t)bi * N_SZ;

    float dv[8]; unsigned ab[8];
    #pragma unroll
    for (int e = 0; e < 8; e++) {
        int idx = tid + e * 256;
        float d = fmaf(gm, crow[idx], xrow[idx]);
        dv[e] = d;
        ab[e] = __float_as_uint(fabsf(d));
    }

    __shared__ int whist[8][256];
    __shared__ int suf[256];
    __shared__ unsigned sh_pref;
    __shared__ int sh_k;
    unsigned prefix = 0; int k = p;

    for (int pass = 0; pass < 4; pass++) {
        int shift = 24 - 8 * pass;
        #pragma unroll
        for (int w = 0; w < 8; w++) whist[w][tid] = 0;
        __syncthreads();
        #pragma unroll
        for (int e = 0; e < 8; e++) {
            if ((unsigned)(((unsigned long long)ab[e]) >> (shift + 8)) == prefix)
                atomicAdd(&whist[warp][(ab[e] >> shift) & 255], 1);
        }
        __syncthreads();
        // per-bin total across the 8 warp copies (thread tid owns bin tid)
        int total = 0;
        #pragma unroll
        for (int w = 0; w < 8; w++) total += whist[w][tid];
        suf[tid] = total;
        __syncthreads();
        // suffix sum: suf[b] = sum_{b' >= b} total[b']  (Hillis-Steele, ping in place)
        #pragma unroll
        for (int o = 1; o < 256; o <<= 1) {
            int v = suf[tid] + ((tid + o < 256) ? suf[tid + o] : 0);
            __syncthreads();
            suf[tid] = v;
            __syncthreads();
        }
        // unique bsel: suf[bsel] >= k and (bsel == 255 or suf[bsel+1] < k)
        if (suf[tid] >= k && (tid == 255 || suf[tid + 1] < k)) {
            sh_pref = (prefix << 8) | (unsigned)tid;
            sh_k = k - (suf[tid] - total);
        }
        __syncthreads();
        prefix = sh_pref; k = sh_k;
        __syncthreads();
    }

    float thresh = __uint_as_float(prefix);  // value of p-th largest |d|
    #pragma unroll
    for (int e = 0; e < 8; e++) {
        int idx = tid + e * 256;
        float d = dv[e], ad = fabsf(d);
        float soft = copysignf(fmaxf(ad - th, 0.f), d);
        float val = (ad > thresh) ? d : soft;
        xrow[idx] = val;
        float h = to_tf32(val);
        hrow[idx] = h;
        lrow[idx] = val - h;
    }
}

// ---------------- host driver (graph-capturable) ----------------
extern "C" void kernel_launch(void* const* d_in, const int* in_sizes, int n_in,
                              void* d_out, int out_size)
{
    const float* y     = (const float*)d_in[0];
    const float* A     = (const float*)d_in[1];
    const float* W_ih  = (const float*)d_in[2];
    const float* W_hh  = (const float*)d_in[3];
    const float* b_ih  = (const float*)d_in[4];
    const float* b_hh  = (const float*)d_in[5];
    const float* W_lll = (const float*)d_in[6];
    const float* b_lll = (const float*)d_in[7];
    const float* W_lin = (const float*)d_in[8];
    const float* b_lin = (const float*)d_in[9];
    const float* h0    = (const float*)d_in[10];
    const float* c0    = (const float*)d_in[11];
    float* x = (float*)d_out;

    float *Ahi, *Alo, *Athi, *Atlo, *bhi, *blo, *xhi, *xlo, *cc, *part;
    float *gates, *hid, *cel, *l1b, *l1c, *gam, *the, *stats;
    cudaGetSymbolAddress((void**)&Ahi,  g_Ahi);
    cudaGetSymbolAddress((void**)&Alo,  g_Alo);
    cudaGetSymbolAddress((void**)&Athi, g_Athi);
    cudaGetSymbolAddress((void**)&Atlo, g_Atlo);
    cudaGetSymbolAddress((void**)&bhi,  g_bhi);
    cudaGetSymbolAddress((void**)&blo,  g_blo);
    cudaGetSymbolAddress((void**)&xhi,  g_xhi);
    cudaGetSymbolAddress((void**)&xlo,  g_xlo);
    cudaGetSymbolAddress((void**)&cc,   g_c);
    cudaGetSymbolAddress((void**)&part, g_part);
    cudaGetSymbolAddress((void**)&gates, g_gates);
    cudaGetSymbolAddress((void**)&hid,  g_hidden);
    cudaGetSymbolAddress((void**)&cel,  g_cell);
    cudaGetSymbolAddress((void**)&l1b,  g_l1b);
    cudaGetSymbolAddress((void**)&l1c,  g_l1c);
    cudaGetSymbolAddress((void**)&gam,  g_gamma);
    cudaGetSymbolAddress((void**)&the,  g_theta);
    cudaGetSymbolAddress((void**)&stats, g_stats);

    // dynamic smem (bytes): stage = (2*BM*20 + 2*BN*20) floats, double-buffered
    constexpr int SMEM1 = 2 * (2 * 128 * 20 + 2 * 64  * 20) * 4;   // 61440 B (128x64)
    constexpr int SMEM2 = 2 * (2 * 128 * 20 + 2 * 128 * 20) * 4;   // 81920 B (128x128)
    cudaFuncSetAttribute((const void*)gemm_mma<128, 64, 4, 2, N_SZ / SPLITK, 2>,
                         cudaFuncAttributeMaxDynamicSharedMemorySize, SMEM1);
    cudaFuncSetAttribute((const void*)gemm_mma<128, 128, 4, 2, M_SZ, 0>,
                         cudaFuncAttributeMaxDynamicSharedMemorySize, SMEM2);

    cudaMemsetAsync(x, 0, sizeof(float) * (size_t)B_SZ * N_SZ, 0);
    split_A<<<dim3(N_SZ/32, M_SZ/32), dim3(32, 8)>>>(A, Ahi, Alo, Athi, Atlo);
    init_hc<<<(B_SZ*DIM_SZ + 255)/256, 256>>>(h0, c0, hid, cel);

    // s_sched = clip(linspace(S/K, S*1.4, K), 0, S*1.2).astype(int32)
    static const int sched[K_ITERS] = {6, 15, 24, 33, 41, 50, 59, 68,
                                       77, 86, 95, 104, 113, 120, 120, 120};

    for (int it = 0; it < K_ITERS; ++it) {
        if (it == 0) {
            split_y<<<B_SZ, 128>>>(y, bhi, blo, l1b, l1c);   // b = y; l1b; zero l1c
        } else {
            // partials = x@A^T over K halves: 128x64 tiles, grid (8,16,2) = 256 CTAs
            gemm_mma<128, 64, 4, 2, N_SZ / SPLITK, 2>
                <<<dim3(M_SZ/64, B_SZ/128, SPLITK), 256, SMEM1>>>(
                xhi, xlo, Ahi, Alo, N_SZ, part, nullptr, M_SZ);
            // b = y - sum partials; hi/lo split; l1b direct; zero l1c
            finalize_b<<<B_SZ, 128>>>(y, part, bhi, blo, l1b, l1c);
        }

        // c = b @ A  (rows=B, cols=N, K=M); 128x128 tiles -> 256 CTAs
        gemm_mma<128, 128, 4, 2, M_SZ, 0><<<dim3(N_SZ/128, B_SZ/128), 256, SMEM2>>>(
            bhi, blo, Athi, Atlo, M_SZ, cc, l1c, N_SZ);

        if (it == 0) stats_kernel<<<1, 256>>>(l1b, l1c, stats);

        // gates = stack @ W_ih^T + b_ih + hidden @ W_hh^T + b_hh
        gemm_cp<64,64,16,4,4,2,0><<<dim3(GATE_SZ/64, B_SZ/64), 256>>>(
            hid, DIM_SZ, W_hh, DIM_SZ, DIM_SZ, nullptr, W_ih, b_ih, b_hh, gates, GATE_SZ, nullptr);

        lstm_update<<<B_SZ/ROWS_PER, DIM_SZ>>>(gates, W_lll, b_lll, W_lin, b_lin,
                                               hid, cel, gam, the);

        // d = x + gamma*c; x = top-p-aware soft threshold; split x -> hi/lo
        threshold_kernel<<<B_SZ, 256>>>(cc, x, xhi, xlo, gam, the, sched[it]);
    }
}

// round 17
// speedup vs baseline: 1.1503x; 1.0323x over previous
#include <cuda_runtime.h>
#include <stdint.h>
#include <math.h>

#define B_SZ 2048
#define M_SZ 512
#define N_SZ 2048
#define DIM_SZ 128
#define GATE_SZ 512
#define K_ITERS 16
#define SPLITK 2

// ---------------- scratch (static device globals; no allocation) ----------------
__device__ float g_Ahi[(size_t)M_SZ * N_SZ];
__device__ float g_Alo[(size_t)M_SZ * N_SZ];
__device__ float g_Athi[(size_t)N_SZ * M_SZ];
__device__ float g_Atlo[(size_t)N_SZ * M_SZ];
__device__ float g_Whhhi[(size_t)GATE_SZ * DIM_SZ];
__device__ float g_Whhlo[(size_t)GATE_SZ * DIM_SZ];
__device__ float g_bhi[(size_t)B_SZ * M_SZ];
__device__ float g_blo[(size_t)B_SZ * M_SZ];
__device__ float g_xhi[(size_t)B_SZ * N_SZ];
__device__ float g_xlo[(size_t)B_SZ * N_SZ];
__device__ float g_c[(size_t)B_SZ * N_SZ];
__device__ float g_part[SPLITK][(size_t)B_SZ * M_SZ];   // split-K partials for GEMM1
__device__ float g_gates[(size_t)B_SZ * GATE_SZ];
__device__ float g_hhi[(size_t)B_SZ * DIM_SZ];
__device__ float g_hlo[(size_t)B_SZ * DIM_SZ];
__device__ float g_cell[(size_t)B_SZ * DIM_SZ];
__device__ float g_l1b[B_SZ];
__device__ float g_l1c[B_SZ];
__device__ float g_gamma[B_SZ];
__device__ float g_theta[B_SZ];
__device__ float g_stats[4];   // mean_b, std_b, mean_c, std_c

// ---------------- PTX helpers (all sm_80-level; compile at compute_100) --------
__device__ __forceinline__ uint32_t smem_u32(const void* p) {
    uint32_t a;
    asm("{ .reg .u64 t; cvta.to.shared.u64 t, %1; cvt.u32.u64 %0, t; }" : "=r"(a) : "l"(p));
    return a;
}
__device__ __forceinline__ float to_tf32(float x) {
    uint32_t r;
    asm("cvt.rna.tf32.f32 %0, %1;" : "=r"(r) : "f"(x));
    return __uint_as_float(r);
}
__device__ __forceinline__ void cp16(uint32_t dst, const void* src) {
    asm volatile("cp.async.cg.shared.global [%0], [%1], 16;\n" :: "r"(dst), "l"(src));
}
__device__ __forceinline__ void cp_commit() {
    asm volatile("cp.async.commit_group;\n" ::: "memory");
}
template<int N>
__device__ __forceinline__ void cp_wait() {
    asm volatile("cp.async.wait_group %0;\n" :: "n"(N) : "memory");
}
// m16n8k8 tf32 MMA, D += A*B (A row-major 16x8, B col-major 8x8)
__device__ __forceinline__ void mma_tf32(float* d, const uint32_t* a, const uint32_t* b) {
    asm volatile(
        "mma.sync.aligned.m16n8k8.row.col.f32.tf32.tf32.f32 "
        "{%0,%1,%2,%3}, {%4,%5,%6,%7}, {%8,%9}, {%0,%1,%2,%3};"
        : "+f"(d[0]), "+f"(d[1]), "+f"(d[2]), "+f"(d[3])
        : "r"(a[0]), "r"(a[1]), "r"(a[2]), "r"(a[3]), "r"(b[0]), "r"(b[1]));
}

// ============================================================================
// GEMM1 (split-K partials): 3xTF32 NT GEMM via mma.sync, templated K.
// CTA: 256 threads = 4x2 warps; tile 128x64, BK=16, cp.async double buffer.
// Writes partial to Cout + blockIdx.z * B*M.
// ============================================================================
template<int BM, int BN, int WM, int WN, int KLEN>
__global__ __launch_bounds__(256, 2)
void gemm_part(const float* __restrict__ Xhi, const float* __restrict__ Xlo,
               const float* __restrict__ Whi, const float* __restrict__ Wlo,
               int ldk, float* __restrict__ Cout, int ldo)
{
    static_assert(WM * WN == 8, "8 warps");
    constexpr int BK = 16;
    constexpr int ST = BK + 4;
    constexpr int SZA = BM * ST;
    constexpr int SZB = BN * ST;
    constexpr int STAGEF = 2 * SZA + 2 * SZB;
    constexpr int T = KLEN / BK;
    constexpr int WTM = BM / WM;
    constexpr int WTN = BN / WN;
    constexpr int MT  = WTM / 16;
    constexpr int NTN = WTN / 8;

    extern __shared__ float sm[];

    const int tid = threadIdx.x;
    const int wid = tid >> 5;
    const int lane = tid & 31;
    const int wm = wid / WN;
    const int wn = wid % WN;
    const int ar = lane >> 2;
    const int ak = lane & 3;
    const int row0 = blockIdx.y * BM;
    const int col0 = blockIdx.x * BN;
    const int koff = blockIdx.z * KLEN;
    float* outp = Cout + (size_t)blockIdx.z * B_SZ * M_SZ;

    float acc[MT][NTN][4];
    #pragma unroll
    for (int mt = 0; mt < MT; mt++)
        #pragma unroll
        for (int nt = 0; nt < NTN; nt++)
            #pragma unroll
            for (int q = 0; q < 4; q++) acc[mt][nt][q] = 0.f;

    auto load_stage = [&](int t, int buf) {
        float* s = sm + buf * STAGEF;
        const int k0 = koff + t * BK;
        for (int c = tid; c < BM * 4; c += 256) {
            int r = c >> 2, kc = c & 3;
            const size_t src = (size_t)(row0 + r) * ldk + k0 + kc * 4;
            cp16(smem_u32(s + r * ST + kc * 4), &Xhi[src]);
            cp16(smem_u32(s + SZA + r * ST + kc * 4), &Xlo[src]);
        }
        for (int c = tid; c < BN * 4; c += 256) {
            int r = c >> 2, kc = c & 3;
            const size_t src = (size_t)(col0 + r) * ldk + k0 + kc * 4;
            cp16(smem_u32(s + 2 * SZA + r * ST + kc * 4), &Whi[src]);
            cp16(smem_u32(s + 2 * SZA + SZB + r * ST + kc * 4), &Wlo[src]);
        }
        cp_commit();
    };

    load_stage(0, 0);
    if (T > 1) load_stage(1, 1);

    for (int t = 0; t < T; t++) {
        if (t + 1 < T) cp_wait<1>(); else cp_wait<0>();
        __syncthreads();
        const float* s = sm + (t & 1) * STAGEF;
        const float* As_hi = s;
        const float* As_lo = s + SZA;
        const float* Bs_hi = s + 2 * SZA;
        const float* Bs_lo = s + 2 * SZA + SZB;

        #pragma unroll
        for (int ks = 0; ks < 2; ks++) {
            const int kk = ks * 8;
            uint32_t ahi[MT][4], alo[MT][4];
            #pragma unroll
            for (int mt = 0; mt < MT; mt++) {
                const float* pa = As_hi + (wm * WTM + mt * 16 + ar) * ST + kk + ak;
                ahi[mt][0] = __float_as_uint(pa[0]);
                ahi[mt][1] = __float_as_uint(pa[8 * ST]);
                ahi[mt][2] = __float_as_uint(pa[4]);
                ahi[mt][3] = __float_as_uint(pa[8 * ST + 4]);
                const float* pl = As_lo + (wm * WTM + mt * 16 + ar) * ST + kk + ak;
                alo[mt][0] = __float_as_uint(pl[0]);
                alo[mt][1] = __float_as_uint(pl[8 * ST]);
                alo[mt][2] = __float_as_uint(pl[4]);
                alo[mt][3] = __float_as_uint(pl[8 * ST + 4]);
            }
            #pragma unroll
            for (int nt = 0; nt < NTN; nt++) {
                uint32_t bhi[2], blo[2];
                const float* pb = Bs_hi + (wn * WTN + nt * 8 + ar) * ST + kk + ak;
                bhi[0] = __float_as_uint(pb[0]);
                bhi[1] = __float_as_uint(pb[4]);
                const float* pc = Bs_lo + (wn * WTN + nt * 8 + ar) * ST + kk + ak;
                blo[0] = __float_as_uint(pc[0]);
                blo[1] = __float_as_uint(pc[4]);
                #pragma unroll
                for (int mt = 0; mt < MT; mt++) {
                    mma_tf32(acc[mt][nt], ahi[mt], bhi);
                    mma_tf32(acc[mt][nt], ahi[mt], blo);
                    mma_tf32(acc[mt][nt], alo[mt], bhi);
                }
            }
        }
        __syncthreads();
        if (t + 2 < T) load_stage(t + 2, t & 1);
    }

    #pragma unroll
    for (int mt = 0; mt < MT; mt++) {
        const int gr0 = row0 + wm * WTM + mt * 16 + ar;
        const int gr1 = gr0 + 8;
        #pragma unroll
        for (int nt = 0; nt < NTN; nt++) {
            const int gc = col0 + wn * WTN + nt * 8 + ak * 2;
            *(float2*)&outp[(size_t)gr0 * ldo + gc] = make_float2(acc[mt][nt][0], acc[mt][nt][1]);
            *(float2*)&outp[(size_t)gr1 * ldo + gc] = make_float2(acc[mt][nt][2], acc[mt][nt][3]);
        }
    }
}

// ============================================================================
// Fused GEMM2 + gates: grid (16+4, 16).
//  blocks x<16:  c = b @ A (K=512), fused l1c row sums (atomic)
//  blocks x>=16: gates_raw = hidden @ W_hh^T (K=128) -- runtime trip count
// Both 128x128 tiles, 3xTF32, same pipeline.
// ============================================================================
__global__ __launch_bounds__(256, 2)
void gemm2_fused(const float* __restrict__ bhi, const float* __restrict__ blo,
                 const float* __restrict__ Athi, const float* __restrict__ Atlo,
                 float* __restrict__ cc, float* __restrict__ l1c,
                 const float* __restrict__ hhi, const float* __restrict__ hlo,
                 const float* __restrict__ whhhi, const float* __restrict__ whhlo,
                 float* __restrict__ gates)
{
    constexpr int BM = 128, BN = 128, WM = 4, WN = 2;
    constexpr int BK = 16;
    constexpr int ST = BK + 4;
    constexpr int SZA = BM * ST;
    constexpr int SZB = BN * ST;
    constexpr int STAGEF = 2 * SZA + 2 * SZB;
    constexpr int WTM = BM / WM;   // 32
    constexpr int WTN = BN / WN;   // 64
    constexpr int MT  = WTM / 16;  // 2
    constexpr int NTN = WTN / 8;   // 8

    extern __shared__ float sm[];

    const bool isG = blockIdx.x >= (N_SZ / BN);
    const float* Xhi = isG ? hhi : bhi;
    const float* Xlo = isG ? hlo : blo;
    const float* Whi = isG ? whhhi : Athi;
    const float* Wlo = isG ? whhlo : Atlo;
    float* outp = isG ? gates : cc;
    const int ldk = isG ? DIM_SZ : M_SZ;
    const int Ktot = isG ? DIM_SZ : M_SZ;
    const int ldo = isG ? GATE_SZ : N_SZ;
    const int Tn = Ktot / BK;      // 8 or 32

    const int tid = threadIdx.x;
    const int wid = tid >> 5;
    const int lane = tid & 31;
    const int wm = wid / WN;
    const int wn = wid % WN;
    const int ar = lane >> 2;
    const int ak = lane & 3;
    const int row0 = blockIdx.y * BM;
    const int col0 = (isG ? blockIdx.x - (N_SZ / BN) : blockIdx.x) * BN;

    float acc[MT][NTN][4];
    #pragma unroll
    for (int mt = 0; mt < MT; mt++)
        #pragma unroll
        for (int nt = 0; nt < NTN; nt++)
            #pragma unroll
            for (int q = 0; q < 4; q++) acc[mt][nt][q] = 0.f;

    auto load_stage = [&](int t, int buf) {
        float* s = sm + buf * STAGEF;
        const int k0 = t * BK;
        for (int c = tid; c < BM * 4; c += 256) {
            int r = c >> 2, kc = c & 3;
            const size_t src = (size_t)(row0 + r) * ldk + k0 + kc * 4;
            cp16(smem_u32(s + r * ST + kc * 4), &Xhi[src]);
            cp16(smem_u32(s + SZA + r * ST + kc * 4), &Xlo[src]);
        }
        for (int c = tid; c < BN * 4; c += 256) {
            int r = c >> 2, kc = c & 3;
            const size_t src = (size_t)(col0 + r) * ldk + k0 + kc * 4;
            cp16(smem_u32(s + 2 * SZA + r * ST + kc * 4), &Whi[src]);
            cp16(smem_u32(s + 2 * SZA + SZB + r * ST + kc * 4), &Wlo[src]);
        }
        cp_commit();
    };

    load_stage(0, 0);
    if (Tn > 1) load_stage(1, 1);

    for (int t = 0; t < Tn; t++) {
        if (t + 1 < Tn) cp_wait<1>(); else cp_wait<0>();
        __syncthreads();
        const float* s = sm + (t & 1) * STAGEF;
        const float* As_hi = s;
        const float* As_lo = s + SZA;
        const float* Bs_hi = s + 2 * SZA;
        const float* Bs_lo = s + 2 * SZA + SZB;

        #pragma unroll
        for (int ks = 0; ks < 2; ks++) {
            const int kk = ks * 8;
            uint32_t ahi[MT][4], alo[MT][4];
            #pragma unroll
            for (int mt = 0; mt < MT; mt++) {
                const float* pa = As_hi + (wm * WTM + mt * 16 + ar) * ST + kk + ak;
                ahi[mt][0] = __float_as_uint(pa[0]);
                ahi[mt][1] = __float_as_uint(pa[8 * ST]);
                ahi[mt][2] = __float_as_uint(pa[4]);
                ahi[mt][3] = __float_as_uint(pa[8 * ST + 4]);
                const float* pl = As_lo + (wm * WTM + mt * 16 + ar) * ST + kk + ak;
                alo[mt][0] = __float_as_uint(pl[0]);
                alo[mt][1] = __float_as_uint(pl[8 * ST]);
                alo[mt][2] = __float_as_uint(pl[4]);
                alo[mt][3] = __float_as_uint(pl[8 * ST + 4]);
            }
            #pragma unroll
            for (int nt = 0; nt < NTN; nt++) {
                uint32_t bhi[2], blo[2];
                const float* pb = Bs_hi + (wn * WTN + nt * 8 + ar) * ST + kk + ak;
                bhi[0] = __float_as_uint(pb[0]);
                bhi[1] = __float_as_uint(pb[4]);
                const float* pc = Bs_lo + (wn * WTN + nt * 8 + ar) * ST + kk + ak;
                blo[0] = __float_as_uint(pc[0]);
                blo[1] = __float_as_uint(pc[4]);
                #pragma unroll
                for (int mt = 0; mt < MT; mt++) {
                    mma_tf32(acc[mt][nt], ahi[mt], bhi);
                    mma_tf32(acc[mt][nt], ahi[mt], blo);
                    mma_tf32(acc[mt][nt], alo[mt], bhi);
                }
            }
        }
        __syncthreads();
        if (t + 2 < Tn) load_stage(t + 2, t & 1);
    }

    float rs[MT * 2];
    #pragma unroll
    for (int i = 0; i < MT * 2; i++) rs[i] = 0.f;
    #pragma unroll
    for (int mt = 0; mt < MT; mt++) {
        const int gr0 = row0 + wm * WTM + mt * 16 + ar;
        const int gr1 = gr0 + 8;
        #pragma unroll
        for (int nt = 0; nt < NTN; nt++) {
            const int gc = col0 + wn * WTN + nt * 8 + ak * 2;
            float v0 = acc[mt][nt][0], v1 = acc[mt][nt][1];
            float v2 = acc[mt][nt][2], v3 = acc[mt][nt][3];
            *(float2*)&outp[(size_t)gr0 * ldo + gc] = make_float2(v0, v1);
            *(float2*)&outp[(size_t)gr1 * ldo + gc] = make_float2(v2, v3);
            if (!isG) {
                rs[mt * 2 + 0] += fabsf(v0) + fabsf(v1);
                rs[mt * 2 + 1] += fabsf(v2) + fabsf(v3);
            }
        }
    }
    if (!isG) {
        #pragma unroll
        for (int i = 0; i < MT * 2; i++) {
            rs[i] += __shfl_xor_sync(0xffffffffu, rs[i], 1);
            rs[i] += __shfl_xor_sync(0xffffffffu, rs[i], 2);
        }
        if (ak == 0) {
            #pragma unroll
            for (int i = 0; i < MT * 2; i++) {
                int r = row0 + wm * WTM + (i >> 1) * 16 + (i & 1) * 8 + ar;
                atomicAdd(&l1c[r], rs[i]);
            }
        }
    }
}

// ---------------- finalize b = y - sum(partials); hi/lo split; l1b; zero l1c ---
__global__ void finalize_b(const float* __restrict__ y,
                           const float* __restrict__ parts,
                           float* __restrict__ bhi, float* __restrict__ blo,
                           float* __restrict__ l1b, float* __restrict__ l1c) {
    int row = blockIdx.x;
    int tid = threadIdx.x;   // 128 threads, 4 elems each
    const size_t base = (size_t)row * M_SZ + tid * 4;
    float4 yv = *(const float4*)&y[base];
    float v0 = yv.x, v1 = yv.y, v2 = yv.z, v3 = yv.w;
    #pragma unroll
    for (int z = 0; z < SPLITK; z++) {
        float4 p = *(const float4*)&parts[(size_t)z * B_SZ * M_SZ + base];
        v0 -= p.x; v1 -= p.y; v2 -= p.z; v3 -= p.w;
    }
    float h0 = to_tf32(v0), h1 = to_tf32(v1), h2 = to_tf32(v2), h3 = to_tf32(v3);
    *(float4*)&bhi[base] = make_float4(h0, h1, h2, h3);
    *(float4*)&blo[base] = make_float4(v0 - h0, v1 - h1, v2 - h2, v3 - h3);
    float s = fabsf(v0) + fabsf(v1) + fabsf(v2) + fabsf(v3);
    __shared__ float red[128];
    red[tid] = s; __syncthreads();
    for (int o = 64; o > 0; o >>= 1) {
        if (tid < o) red[tid] += red[tid + o];
        __syncthreads();
    }
    if (tid == 0) { l1b[row] = red[0]; l1c[row] = 0.f; }
}

// ---------------- prologue: split A (+transpose) and W_hh into hi/lo ----------
__global__ void split_A(const float* __restrict__ A,
                        float* __restrict__ Ahi, float* __restrict__ Alo,
                        float* __restrict__ Athi, float* __restrict__ Atlo) {
    __shared__ float th[32][33], tl[32][33];
    int n0 = blockIdx.x * 32, m0 = blockIdx.y * 32;
    int tx = threadIdx.x, ty = threadIdx.y;   // block (32, 8)
    #pragma unroll
    for (int i = 0; i < 32; i += 8) {
        size_t idx = (size_t)(m0 + ty + i) * N_SZ + n0 + tx;
        float a = A[idx];
        float h = to_tf32(a), l = a - h;
        Ahi[idx] = h; Alo[idx] = l;
        th[ty + i][tx] = h; tl[ty + i][tx] = l;
    }
    __syncthreads();
    #pragma unroll
    for (int i = 0; i < 32; i += 8) {
        size_t idx = (size_t)(n0 + ty + i) * M_SZ + m0 + tx;
        Athi[idx] = th[tx][ty + i];
        Atlo[idx] = tl[tx][ty + i];
    }
}

__global__ void split_Whh(const float* __restrict__ W,
                          float* __restrict__ Whi, float* __restrict__ Wlo) {
    int idx = blockIdx.x * blockDim.x + threadIdx.x;
    if (idx < GATE_SZ * DIM_SZ) {
        float w = W[idx];
        float h = to_tf32(w);
        Whi[idx] = h; Wlo[idx] = w - h;
    }
}

// ---------------- iter 0: b = y; hi/lo split + l1b; zero l1c ----------------
__global__ void split_y(const float* __restrict__ y,
                        float* __restrict__ bhi, float* __restrict__ blo,
                        float* __restrict__ l1b, float* __restrict__ l1c) {
    int row = blockIdx.x;
    int tid = threadIdx.x;   // 128
    const float* p = y + (size_t)row * M_SZ;
    float4 v = *(const float4*)&p[tid * 4];
    float h0 = to_tf32(v.x), h1 = to_tf32(v.y), h2 = to_tf32(v.z), h3 = to_tf32(v.w);
    *(float4*)&bhi[(size_t)row * M_SZ + tid * 4] = make_float4(h0, h1, h2, h3);
    *(float4*)&blo[(size_t)row * M_SZ + tid * 4] = make_float4(v.x - h0, v.y - h1, v.z - h2, v.w - h3);
    float s = fabsf(v.x) + fabsf(v.y) + fabsf(v.z) + fabsf(v.w);
    __shared__ float red[128];
    red[tid] = s; __syncthreads();
    for (int o = 64; o > 0; o >>= 1) {
        if (tid < o) red[tid] += red[tid + o];
        __syncthreads();
    }
    if (tid == 0) { l1b[row] = red[0]; l1c[row] = 0.f; }
}

// ---------------- init hidden(hi/lo)/cell from h0/c0 ----------------
__global__ void init_hc(const float* __restrict__ h0, const float* __restrict__ c0,
                        float* __restrict__ hhi, float* __restrict__ hlo,
                        float* __restrict__ cell) {
    int idx = blockIdx.x * blockDim.x + threadIdx.x;
    if (idx < B_SZ * DIM_SZ) {
        int j = idx & (DIM_SZ - 1);
        float h = h0[j];
        float hh = to_tf32(h);
        hhi[idx] = hh; hlo[idx] = h - hh;
        cell[idx] = c0[j];
    }
}

// ---------------- stats (mean + ddof=1 std), double accumulation ----------------
__global__ void stats_kernel(const float* __restrict__ l1b,
                             const float* __restrict__ l1c,
                             float* __restrict__ stats) {
    int tid = threadIdx.x;
    double sb = 0, sb2 = 0, sc = 0, sc2 = 0;
    for (int i = tid; i < B_SZ; i += 256) {
        double v = (double)l1b[i]; sb += v; sb2 += v*v;
        double w = (double)l1c[i]; sc += w; sc2 += w*w;
    }
    __shared__ double red[256];
    auto reduce = [&](double v) -> double {
        red[tid] = v; __syncthreads();
        for (int o = 128; o > 0; o >>= 1) {
            if (tid < o) red[tid] += red[tid + o];
            __syncthreads();
        }
        double r = red[0]; __syncthreads();
        return r;
    };
    double Sb = reduce(sb), Sb2 = reduce(sb2), Sc = reduce(sc), Sc2 = reduce(sc2);
    if (tid == 0) {
        double nb = (double)B_SZ;
        double mb = Sb / nb, mc = Sc / nb;
        double vb = (Sb2 - Sb*Sb/nb) / (nb - 1.0);
        double vc = (Sc2 - Sc*Sc/nb) / (nb - 1.0);
        stats[0] = (float)mb; stats[1] = (float)sqrt(vb);
        stats[2] = (float)mc; stats[3] = (float)sqrt(vc);
    }
}

// ---------------- LSTM pointwise + output head (gate affine fused in) ---------
#define ROWS_PER 2
__global__ void lstm_update(const float* __restrict__ gates,
                            const float* __restrict__ Wih,
                            const float* __restrict__ bih, const float* __restrict__ bhh,
                            const float* __restrict__ Wlll, const float* __restrict__ blll,
                            const float* __restrict__ Wlin, const float* __restrict__ blin,
                            float* __restrict__ hhi, float* __restrict__ hlo,
                            float* __restrict__ cell,
                            float* __restrict__ gamma, float* __restrict__ theta)
{
    int j = threadIdx.x;   // 0..127
    int base = blockIdx.x * ROWS_PER;
    __shared__ float c2sh[DIM_SZ];
    __shared__ float r0[DIM_SZ], r1[DIM_SZ];
    for (int r = 0; r < ROWS_PER; r++) {
        int bi = base + r;
        float s0 = (g_l1b[bi] - g_stats[0]) / g_stats[1];
        float s1 = (g_l1c[bi] - g_stats[2]) / g_stats[3];
        const float* g = gates + (size_t)bi * GATE_SZ;
        float gv[4];
        #pragma unroll
        for (int q = 0; q < 4; q++) {
            int cq = q * DIM_SZ + j;
            gv[q] = g[cq] + (s0 * Wih[cq*2 + 0] + s1 * Wih[cq*2 + 1]
                             + bih[cq] + bhh[cq]);
        }
        float cprev = cell[(size_t)bi * DIM_SZ + j];
        float ii = 1.f / (1.f + expf(-gv[0]));
        float ff = 1.f / (1.f + expf(-gv[1]));
        float oo = 1.f / (1.f + expf(-gv[3]));
        float c2 = ff * cprev + ii * tanhf(gv[2]);
        float h2 = oo * tanhf(c2);
        cell[(size_t)bi * DIM_SZ + j] = c2;
        float hh = to_tf32(h2);
        hhi[(size_t)bi * DIM_SZ + j] = hh;
        hlo[(size_t)bi * DIM_SZ + j] = h2 - hh;
        c2sh[j] = c2;
        __syncthreads();
        float acc = blll[j];
        #pragma unroll 8
        for (int k = 0; k < DIM_SZ; k++)
            acc = fmaf(c2sh[k], __ldg(&Wlll[j * DIM_SZ + k]), acc);
        float t = fmaxf(acc, 0.f);
        r0[j] = t * Wlin[j];
        r1[j] = t * Wlin[DIM_SZ + j];
        __syncthreads();
        for (int o = 64; o > 0; o >>= 1) {
            if (j < o) { r0[j] += r0[j + o]; r1[j] += r1[j + o]; }
            __syncthreads();
        }
        if (j == 0) {
            float a0 = r0[0] + blin[0], a1 = r1[0] + blin[1];
            gamma[bi] = fmaxf(a0, 0.f) + log1pf(expf(-fabsf(a0)));
            theta[bi] = fmaxf(a1, 0.f) + log1pf(expf(-fabsf(a1)));
        }
        __syncthreads();
    }
}

// ---------------- soft-threshold with top-p keep (parallel radix select) -------
__global__ void threshold_kernel(const float* __restrict__ c, float* __restrict__ x,
                                 float* __restrict__ xhi, float* __restrict__ xlo,
                                 const float* __restrict__ gamma,
                                 const float* __restrict__ theta, int p)
{
    int bi = blockIdx.x;
    int tid = threadIdx.x;   // 256 threads, 8 elems each
    int warp = tid >> 5;
    float gm = gamma[bi], th = theta[bi];
    const float* crow = c + (size_t)bi * N_SZ;
    float* xrow = x + (size_t)bi * N_SZ;
    float* hrow = xhi + (size_t)bi * N_SZ;
    float* lrow = xlo + (size_t)bi * N_SZ;

    float dv[8]; unsigned ab[8];
    #pragma unroll
    for (int e = 0; e < 8; e++) {
        int idx = tid + e * 256;
        float d = fmaf(gm, crow[idx], xrow[idx]);
        dv[e] = d;
        ab[e] = __float_as_uint(fabsf(d));
    }

    __shared__ int whist[8][256];
    __shared__ int suf[256];
    __shared__ unsigned sh_pref;
    __shared__ int sh_k;
    unsigned prefix = 0; int k = p;

    for (int pass = 0; pass < 4; pass++) {
        int shift = 24 - 8 * pass;
        #pragma unroll
        for (int w = 0; w < 8; w++) whist[w][tid] = 0;
        __syncthreads();
        #pragma unroll
        for (int e = 0; e < 8; e++) {
            if ((unsigned)(((unsigned long long)ab[e]) >> (shift + 8)) == prefix)
                atomicAdd(&whist[warp][(ab[e] >> shift) & 255], 1);
        }
        __syncthreads();
        int total = 0;
        #pragma unroll
        for (int w = 0; w < 8; w++) total += whist[w][tid];
        suf[tid] = total;
        __syncthreads();
        #pragma unroll
        for (int o = 1; o < 256; o <<= 1) {
            int v = suf[tid] + ((tid + o < 256) ? suf[tid + o] : 0);
            __syncthreads();
            suf[tid] = v;
            __syncthreads();
        }
        if (suf[tid] >= k && (tid == 255 || suf[tid + 1] < k)) {
            sh_pref = (prefix << 8) | (unsigned)tid;
            sh_k = k - (suf[tid] - total);
        }
        __syncthreads();
        prefix = sh_pref; k = sh_k;
        __syncthreads();
    }

    float thresh = __uint_as_float(prefix);
    #pragma unroll
    for (int e = 0; e < 8; e++) {
        int idx = tid + e * 256;
        float d = dv[e], ad = fabsf(d);
        float soft = copysignf(fmaxf(ad - th, 0.f), d);
        float val = (ad > thresh) ? d : soft;
        xrow[idx] = val;
        float h = to_tf32(val);
        hrow[idx] = h;
        lrow[idx] = val - h;
    }
}

// ---------------- host driver (graph-capturable) ----------------
extern "C" void kernel_launch(void* const* d_in, const int* in_sizes, int n_in,
                              void* d_out, int out_size)
{
    const float* y     = (const float*)d_in[0];
    const float* A     = (const float*)d_in[1];
    const float* W_ih  = (const float*)d_in[2];
    const float* W_hh  = (const float*)d_in[3];
    const float* b_ih  = (const float*)d_in[4];
    const float* b_hh  = (const float*)d_in[5];
    const float* W_lll = (const float*)d_in[6];
    const float* b_lll = (const float*)d_in[7];
    const float* W_lin = (const float*)d_in[8];
    const float* b_lin = (const float*)d_in[9];
    const float* h0    = (const float*)d_in[10];
    const float* c0    = (const float*)d_in[11];
    float* x = (float*)d_out;

    float *Ahi, *Alo, *Athi, *Atlo, *Whhhi, *Whhlo, *bhi, *blo, *xhi, *xlo, *cc, *part;
    float *gates, *hhi, *hlo, *cel, *l1b, *l1c, *gam, *the, *stats;
    cudaGetSymbolAddress((void**)&Ahi,   g_Ahi);
    cudaGetSymbolAddress((void**)&Alo,   g_Alo);
    cudaGetSymbolAddress((void**)&Athi,  g_Athi);
    cudaGetSymbolAddress((void**)&Atlo,  g_Atlo);
    cudaGetSymbolAddress((void**)&Whhhi, g_Whhhi);
    cudaGetSymbolAddress((void**)&Whhlo, g_Whhlo);
    cudaGetSymbolAddress((void**)&bhi,   g_bhi);
    cudaGetSymbolAddress((void**)&blo,   g_blo);
    cudaGetSymbolAddress((void**)&xhi,   g_xhi);
    cudaGetSymbolAddress((void**)&xlo,   g_xlo);
    cudaGetSymbolAddress((void**)&cc,    g_c);
    cudaGetSymbolAddress((void**)&part,  g_part);
    cudaGetSymbolAddress((void**)&gates, g_gates);
    cudaGetSymbolAddress((void**)&hhi,   g_hhi);
    cudaGetSymbolAddress((void**)&hlo,   g_hlo);
    cudaGetSymbolAddress((void**)&cel,   g_cell);
    cudaGetSymbolAddress((void**)&l1b,   g_l1b);
    cudaGetSymbolAddress((void**)&l1c,   g_l1c);
    cudaGetSymbolAddress((void**)&gam,   g_gamma);
    cudaGetSymbolAddress((void**)&the,   g_theta);
    cudaGetSymbolAddress((void**)&stats, g_stats);

    // dynamic smem (bytes): stage = (2*BM*20 + 2*BN*20) floats, double-buffered
    constexpr int SMEM1 = 2 * (2 * 128 * 20 + 2 * 64  * 20) * 4;   // 61440 B (128x64)
    constexpr int SMEM2 = 2 * (2 * 128 * 20 + 2 * 128 * 20) * 4;   // 81920 B (128x128)
    cudaFuncSetAttribute((const void*)gemm_part<128, 64, 4, 2, N_SZ / SPLITK>,
                         cudaFuncAttributeMaxDynamicSharedMemorySize, SMEM1);
    cudaFuncSetAttribute((const void*)gemm2_fused,
                         cudaFuncAttributeMaxDynamicSharedMemorySize, SMEM2);

    cudaMemsetAsync(x, 0, sizeof(float) * (size_t)B_SZ * N_SZ, 0);
    split_A<<<dim3(N_SZ/32, M_SZ/32), dim3(32, 8)>>>(A, Ahi, Alo, Athi, Atlo);
    split_Whh<<<(GATE_SZ*DIM_SZ + 255)/256, 256>>>(W_hh, Whhhi, Whhlo);
    init_hc<<<(B_SZ*DIM_SZ + 255)/256, 256>>>(h0, c0, hhi, hlo, cel);

    // s_sched = clip(linspace(S/K, S*1.4, K), 0, S*1.2).astype(int32)
    static const int sched[K_ITERS] = {6, 15, 24, 33, 41, 50, 59, 68,
                                       77, 86, 95, 104, 113, 120, 120, 120};

    for (int it = 0; it < K_ITERS; ++it) {
        if (it == 0) {
            split_y<<<B_SZ, 128>>>(y, bhi, blo, l1b, l1c);   // b = y; l1b; zero l1c
        } else {
            // partials = x@A^T over K halves: 128x64 tiles, grid (8,16,2) = 256 CTAs
            gemm_part<128, 64, 4, 2, N_SZ / SPLITK>
                <<<dim3(M_SZ/64, B_SZ/128, SPLITK), 256, SMEM1>>>(
                xhi, xlo, Ahi, Alo, N_SZ, part, M_SZ);
            // b = y - sum partials; hi/lo split; l1b direct; zero l1c
            finalize_b<<<B_SZ, 128>>>(y, part, bhi, blo, l1b, l1c);
        }

        // fused: c = b@A (blocks x<16, l1c atomics) + gates_raw = h@W_hh^T (x>=16)
        gemm2_fused<<<dim3(N_SZ/128 + GATE_SZ/128, B_SZ/128), 256, SMEM2>>>(
            bhi, blo, Athi, Atlo, cc, l1c, hhi, hlo, Whhhi, Whhlo, gates);

        if (it == 0) stats_kernel<<<1, 256>>>(l1b, l1c, stats);

        // lstm: applies s0/s1*W_ih + biases to raw gates, then pointwise + head
        lstm_update<<<B_SZ/ROWS_PER, DIM_SZ>>>(gates, W_ih, b_ih, b_hh,
                                               W_lll, b_lll, W_lin, b_lin,
                                               hhi, hlo, cel, gam, the);

        // d = x + gamma*c; x = top-p-aware soft threshold; split x -> hi/lo
        threshold_kernel<<<B_SZ, 256>>>(cc, x, xhi, xlo, gam, the, sched[it]);
    }
}